// round 10
// baseline (speedup 1.0000x reference)
#include <cuda_runtime.h>
#include <cuda_fp16.h>
#include <math.h>
#include <stdint.h>

// Problem constants
#define BB   8
#define SS   1024
#define DD   1024
#define HH   16
#define HD   64
#define MROWS (BB*SS)   // 8192
#define NCHUNK 32       // K / 32
#define NEG_INF (-INFINITY)
#define QSCALE 0.18033688011112042f   // 0.125 * log2(e)

// Scratch (allocation-free rule: __device__ globals)
// Packed fp16 hi/lo operands: layout [row][kchunk(32)][hi 32 | lo 32]
__device__ __half g_xc [MROWS*2048];
__device__ __half g_ac [MROWS*2048];
__device__ __half g_wqc[DD*2048];
__device__ __half g_wkc[DD*2048];
__device__ __half g_wvc[DD*2048];
__device__ __half g_woc[DD*2048];
// Split Q planes + single-plane K/V [B,H,S,HD] fp16 (Q pre-scaled by QSCALE)
__device__ __half g_qh[MROWS*DD], g_ql[MROWS*DD];
__device__ __half g_kh[MROWS*DD];
__device__ __half g_vh[MROWS*DD];
__device__ float g_vb[MROWS];

// ---------------------------------------------------------------------------
// PTX helpers
// ---------------------------------------------------------------------------
__device__ __forceinline__ uint32_t smem_u32(const void* p) {
    uint32_t a;
    asm("{ .reg .u64 t; cvta.to.shared.u64 t, %1; cvt.u32.u64 %0, t; }" : "=r"(a) : "l"(p));
    return a;
}
__device__ __forceinline__ void cp16(uint32_t dst, const void* src) {
    asm volatile("cp.async.cg.shared.global [%0], [%1], 16;" :: "r"(dst), "l"(src));
}
#define CP_COMMIT() asm volatile("cp.async.commit_group;" ::: "memory")
#define CP_WAIT(n)  asm volatile("cp.async.wait_group %0;" :: "n"(n) : "memory")

__device__ __forceinline__ void ldsm4(uint32_t* r, uint32_t addr) {
    asm volatile("ldmatrix.sync.aligned.m8n8.x4.shared.b16 {%0,%1,%2,%3}, [%4];"
                 : "=r"(r[0]), "=r"(r[1]), "=r"(r[2]), "=r"(r[3]) : "r"(addr));
}
__device__ __forceinline__ void ldsm4t(uint32_t* r, uint32_t addr) {
    asm volatile("ldmatrix.sync.aligned.m8n8.x4.trans.shared.b16 {%0,%1,%2,%3}, [%4];"
                 : "=r"(r[0]), "=r"(r[1]), "=r"(r[2]), "=r"(r[3]) : "r"(addr));
}
__device__ __forceinline__ void mma_f16(float* d, const uint32_t* a, const uint32_t* b) {
    asm volatile("mma.sync.aligned.m16n8k16.row.col.f32.f16.f16.f32 "
                 "{%0,%1,%2,%3}, {%4,%5,%6,%7}, {%8,%9}, {%0,%1,%2,%3};"
                 : "+f"(d[0]), "+f"(d[1]), "+f"(d[2]), "+f"(d[3])
                 : "r"(a[0]), "r"(a[1]), "r"(a[2]), "r"(a[3]), "r"(b[0]), "r"(b[1]));
}
__device__ __forceinline__ void splitpack(float x, float y, uint32_t& hi, uint32_t& lo) {
    __half2 h2 = __floats2half2_rn(x, y);
    memcpy(&hi, &h2, 4);
    __half2 l2 = __floats2half2_rn(x - __low2float(h2), y - __high2float(h2));
    memcpy(&lo, &l2, 4);
}

// ---------------------------------------------------------------------------
// Split-convert: fp32 [rows][1024] -> packed fp16 [rows][32][hi32|lo32]
// ---------------------------------------------------------------------------
__device__ __forceinline__ void convert_body(
    const float* __restrict__ in, __half* __restrict__ out, int g)
{
    const int row  = g >> 7;
    const int w    = g & 127;
    const int kc   = w >> 2;
    const int part = w & 3;

    const float* src = in + (size_t)row * 1024 + kc * 32 + part * 8;
    float4 f0 = *(const float4*)(src);
    float4 f1 = *(const float4*)(src + 4);
    const float xs[8] = {f0.x, f0.y, f0.z, f0.w, f1.x, f1.y, f1.z, f1.w};

    alignas(16) __half h[8];
    alignas(16) __half l[8];
    #pragma unroll
    for (int e = 0; e < 8; e++) {
        h[e] = __float2half_rn(xs[e]);
        l[e] = __float2half_rn(xs[e] - __half2float(h[e]));
    }
    __half* dst = out + ((size_t)row * 32 + kc) * 64 + part * 8;
    *(uint4*)(dst)      = *(const uint4*)h;
    *(uint4*)(dst + 32) = *(const uint4*)l;
}

__global__ __launch_bounds__(256) void convert_split(
    const float* __restrict__ in, __half* __restrict__ out, int rows)
{
    const int g = blockIdx.x * 256 + threadIdx.x;
    if (g < rows * 128) convert_body(in, out, g);
}

// Fused weight converts: grid (512, 4)
__global__ __launch_bounds__(256) void convert_w4(
    const float* __restrict__ w0, const float* __restrict__ w1,
    const float* __restrict__ w2, const float* __restrict__ w3,
    __half* o0, __half* o1, __half* o2, __half* o3)
{
    const int g = blockIdx.x * 256 + threadIdx.x;
    const int z = blockIdx.y;
    const float* in    = (z == 0) ? w0 : (z == 1) ? w1 : (z == 2) ? w2 : w3;
    __half* out        = (z == 0) ? o0 : (z == 1) ? o1 : (z == 2) ? o2 : o3;
    if (g < DD * 128) convert_body(in, out, g);
}

// Pad-mask: vb[i] = ids[i]!=1 ? 0 : -INF
__global__ void pad_mask(const long long* __restrict__ ids, float* __restrict__ vb) {
    int i = blockIdx.x * 256 + threadIdx.x;
    if (i < MROWS) vb[i] = (ids[i] != 1LL) ? 0.f : NEG_INF;
}

// ---------------------------------------------------------------------------
// GEMM core: fp16 2-term split via mma.sync. C = (Ah+Al)*Wh^T (+bias)*scale.
// MMA issue order: all 8 hi-plane MMAs first, then all 8 lo-plane MMAs,
// so RAW pairs into the same accumulator are 8 issues apart.
// ---------------------------------------------------------------------------
#define GSTAGE 24576

__device__ __forceinline__ void gemm_core(
    const __half* __restrict__ Ap, const __half* __restrict__ Bp,
    const float* __restrict__ bias, float* __restrict__ outf,
    __half* __restrict__ oh, __half* __restrict__ ol,
    float scale, int mode, char* dsm, int bm, int bn)
{
    const uint32_t smem_base = smem_u32(dsm);
    const int tid  = threadIdx.x;
    const int wid  = tid >> 5;
    const int lane = tid & 31;
    const int wm = (wid & 3) << 5;
    const int wn = (wid >> 2) << 6;

    auto load_stage = [&](int kc, int s) {
        const uint32_t sA = smem_base + s * GSTAGE;
        const uint32_t sB = sA + 16384;
        // A: 128 rows x 128B (hi+lo)
        #pragma unroll
        for (int v = 0; v < 4; v++) {
            const int cid = v * 256 + tid;
            const int row = cid >> 3;
            const int c   = cid & 7;
            cp16(sA + row * 128 + ((c ^ (row & 7)) << 4),
                 Ap + (((size_t)(bm + row) * 32 + kc) << 6) + c * 8);
        }
        // B: 128 rows x 64B (hi only)
        #pragma unroll
        for (int v = 0; v < 2; v++) {
            const int cid = v * 256 + tid;
            const int row = cid >> 2;
            const int c   = cid & 3;
            cp16(sB + row * 64 + ((c ^ ((row >> 1) & 3)) << 4),
                 Bp + (((size_t)(bn + row) * 32 + kc) << 6) + c * 8);
        }
        CP_COMMIT();
    };

    float acc[2][8][4];
    #pragma unroll
    for (int i = 0; i < 2; i++)
        #pragma unroll
        for (int j = 0; j < 8; j++)
            #pragma unroll
            for (int e = 0; e < 4; e++) acc[i][j][e] = 0.f;

    load_stage(0, 0);
    load_stage(1, 1);

    int stage = 0;
    for (int i = 0; i < NCHUNK; i++) {
        CP_WAIT(1);
        __syncthreads();

        const uint32_t sA = smem_base + stage * GSTAGE;
        const uint32_t sB = sA + 16384;

        #pragma unroll
        for (int ks = 0; ks < 2; ks++) {
            uint32_t Ah[2][4], Al[2][4];
            const int chi = ks * 2 + (lane >> 4);   // 0..3 (hi half of A rows)
            const int clo = chi + 4;                // lo half

            #pragma unroll
            for (int f = 0; f < 2; f++) {
                const int r = wm + f * 16 + (lane & 15);
                const uint32_t rb = sA + r * 128;
                ldsm4(Ah[f], rb + ((chi ^ (r & 7)) << 4));
                ldsm4(Al[f], rb + ((clo ^ (r & 7)) << 4));
            }
            #pragma unroll
            for (int ph = 0; ph < 2; ph++) {
                uint32_t Bh[4][2];
                #pragma unroll
                for (int pp = 0; pp < 2; pp++) {
                    const int p = ph * 2 + pp;
                    const int r = wn + p * 16 + (lane & 15);
                    uint32_t q[4];
                    ldsm4(q, sB + r * 64 + ((chi ^ ((r >> 1) & 3)) << 4));
                    Bh[2*pp][0] = q[0]; Bh[2*pp][1] = q[2];
                    Bh[2*pp+1][0] = q[1]; Bh[2*pp+1][1] = q[3];
                }
                // hi-plane pass: 8 independent accumulators
                #pragma unroll
                for (int f = 0; f < 2; f++)
                    #pragma unroll
                    for (int jj = 0; jj < 4; jj++)
                        mma_f16(acc[f][ph * 4 + jj], Ah[f], Bh[jj]);
                // lo-plane pass: RAW on each acc is now 8 issues apart
                #pragma unroll
                for (int f = 0; f < 2; f++)
                    #pragma unroll
                    for (int jj = 0; jj < 4; jj++)
                        mma_f16(acc[f][ph * 4 + jj], Al[f], Bh[jj]);
            }
        }

        if (i + 2 < NCHUNK) {
            int ws = stage + 2; if (ws >= 3) ws -= 3;
            load_stage(i + 2, ws);
        }
        if (++stage == 3) stage = 0;
    }

    #pragma unroll
    for (int f = 0; f < 2; f++) {
        #pragma unroll
        for (int j = 0; j < 8; j++) {
            const int col = bn + wn + j * 8 + ((lane & 3) << 1);
            const float b0 = bias[col], b1 = bias[col + 1];
            #pragma unroll
            for (int half = 0; half < 2; half++) {
                const int m = bm + wm + f * 16 + (lane >> 2) + half * 8;
                float2 o;
                o.x = (acc[f][j][half * 2 + 0] + b0) * scale;
                o.y = (acc[f][j][half * 2 + 1] + b1) * scale;
                if (mode == 0) {
                    *(float2*)(outf + (size_t)m * DD + col) = o;
                } else {
                    const int b_ = m >> 10, s_ = m & 1023;
                    const int h_ = col >> 6, d_ = col & 63;
                    const size_t idx = ((size_t)(b_ * HH + h_) * SS + s_) * HD + d_;
                    uint32_t hi, lo;
                    splitpack(o.x, o.y, hi, lo);
                    *(uint32_t*)(oh + idx) = hi;
                    if (ol) *(uint32_t*)(ol + idx) = lo;
                }
            }
        }
    }
}

// Fused QKV projections: grid (8, 64, 3). Q gets split planes; K,V hi only.
__global__ __launch_bounds__(256, 2) void gemm_qkv(
    const __half* __restrict__ xc,
    const __half* __restrict__ wq, const __half* __restrict__ wk,
    const __half* __restrict__ wv,
    const float* __restrict__ bq, const float* __restrict__ bk,
    const float* __restrict__ bv,
    __half* qh, __half* ql, __half* kh, __half* vh)
{
    extern __shared__ char dsm[];
    const int z = blockIdx.z;
    const __half* Bp   = (z == 0) ? wq : (z == 1) ? wk : wv;
    const float* bias  = (z == 0) ? bq : (z == 1) ? bk : bv;
    __half* oh         = (z == 0) ? qh : (z == 1) ? kh : vh;
    __half* ol         = (z == 0) ? ql : nullptr;
    const float scale  = (z == 0) ? QSCALE : 1.f;
    gemm_core(xc, Bp, bias, nullptr, oh, ol, scale, 1, dsm,
              blockIdx.y << 7, blockIdx.x << 7);
}

__global__ __launch_bounds__(256, 2) void gemm_ao(
    const __half* __restrict__ ac, const __half* __restrict__ woc,
    const float* __restrict__ bo, float* __restrict__ out)
{
    extern __shared__ char dsm[];
    gemm_core(ac, woc, bo, out, nullptr, nullptr, 1.f, 0, dsm,
              blockIdx.y << 7, blockIdx.x << 7);
}

// ---------------------------------------------------------------------------
// Flash attention, fp16 mma.sync 2-term. 64-row q tiles, 128 threads/4 warps.
// Grid (16,16,8). Q split (Qh,Ql); K,V single plane. exp2-domain softmax.
// MMA issue reordered: hi pass over all 8 accs, then lo pass.
// ---------------------------------------------------------------------------
#define FSTAGE 16384

__global__ __launch_bounds__(128) void flash_f16(
    const __half* __restrict__ qh, const __half* __restrict__ ql,
    const __half* __restrict__ kh, const __half* __restrict__ vh,
    const float* __restrict__ vb, __half* __restrict__ outp)
{
    extern __shared__ char dsm[];
    const uint32_t sb = smem_u32(dsm);

    const int tid  = threadIdx.x;
    const int wid  = tid >> 5;
    const int lane = tid & 31;
    const int qt = blockIdx.x, h = blockIdx.y, b = blockIdx.z;
    const size_t bhrow = ((size_t)b * HH + h) * SS;

    const uint32_t sQh = sb, sQl = sb + 8192;
    const uint32_t sVB = sb + 16384;
    const float* svp = (const float*)(dsm + 16384);
    const uint32_t stage_base = sb + 20480;

    auto ldplane = [&](uint32_t dst, const __half* src) {
        #pragma unroll
        for (int v = 0; v < 4; v++) {
            const int cid = v * 128 + tid;
            const int row = cid >> 3, c = cid & 7;
            cp16(dst + row * 128 + ((c ^ (row & 7)) << 4),
                 src + (size_t)row * 64 + c * 8);
        }
    };
    auto load_stage = [&](int kt, int s) {
        const uint32_t st = stage_base + (uint32_t)s * FSTAGE;
        const size_t ro = (bhrow + (size_t)kt * 64) * 64;
        ldplane(st,        kh + ro);
        ldplane(st + 8192, vh + ro);
        CP_COMMIT();
    };

    {
        const size_t qo = (bhrow + (size_t)qt * 64) * 64;
        ldplane(sQh, qh + qo);
        ldplane(sQl, ql + qo);
        #pragma unroll
        for (int v = 0; v < 2; v++) {
            const int cid = v * 128 + tid;
            cp16(sVB + cid * 16, vb + (size_t)b * SS + cid * 4);
        }
        CP_COMMIT();
    }
    load_stage(0, 0);

    uint32_t Qh[4][4], Ql[4][4];
    float O[8][4];
    #pragma unroll
    for (int j = 0; j < 8; j++)
        #pragma unroll
        for (int e = 0; e < 4; e++) O[j][e] = 0.f;
    float mrow0 = NEG_INF, mrow1 = NEG_INF;
    float lp0 = 0.f, lp1 = 0.f;

    const int grp = lane >> 3, rw = lane & 7;
    const int c0  = (lane & 3) << 1;
    const int qr0 = wid * 16 + (lane >> 2);
    const int qr1 = qr0 + 8;

    for (int kt = 0; kt <= qt; kt++) {
        const int s = kt & 1;
        if (kt < qt) { load_stage(kt + 1, s ^ 1); CP_WAIT(1); }
        else         { CP_WAIT(0); }
        __syncthreads();

        if (kt == 0) {
            #pragma unroll
            for (int ks = 0; ks < 4; ks++) {
                const int row = wid * 16 + (grp & 1) * 8 + rw;
                const int ch  = 2 * ks + (grp >> 1);
                const uint32_t off = row * 128 + ((ch ^ (row & 7)) << 4);
                ldsm4(Qh[ks], sQh + off);
                ldsm4(Ql[ks], sQl + off);
            }
        }

        const uint32_t stK = stage_base + (uint32_t)s * FSTAGE;
        const uint32_t stV = stK + 8192;

        float S[8][4];
        #pragma unroll
        for (int j = 0; j < 8; j++)
            #pragma unroll
            for (int e = 0; e < 4; e++) S[j][e] = 0.f;

        #pragma unroll
        for (int ks = 0; ks < 4; ks++) {
            uint32_t Bh[8][2];
            #pragma unroll
            for (int jp = 0; jp < 4; jp++) {
                const int row = jp * 16 + (grp >> 1) * 8 + rw;
                const int ch  = 2 * ks + (grp & 1);
                uint32_t t[4];
                ldsm4(t, stK + row * 128 + ((ch ^ (row & 7)) << 4));
                Bh[2*jp][0] = t[0]; Bh[2*jp][1] = t[1];
                Bh[2*jp+1][0] = t[2]; Bh[2*jp+1][1] = t[3];
            }
            #pragma unroll
            for (int j = 0; j < 8; j++)
                mma_f16(S[j], Qh[ks], Bh[j]);
            #pragma unroll
            for (int j = 0; j < 8; j++)
                mma_f16(S[j], Ql[ks], Bh[j]);
        }

        // mask (pad bias is 0/-INF; S in log2 units)
        #pragma unroll
        for (int j = 0; j < 8; j++) {
            const int k0 = j * 8 + c0, k1 = k0 + 1;
            const float p0 = svp[kt * 64 + k0];
            const float p1 = svp[kt * 64 + k1];
            S[j][0] += p0; S[j][1] += p1; S[j][2] += p0; S[j][3] += p1;
            if (kt == qt) {
                if (k0 > qr0) S[j][0] = NEG_INF;
                if (k1 > qr0) S[j][1] = NEG_INF;
                if (k0 > qr1) S[j][2] = NEG_INF;
                if (k1 > qr1) S[j][3] = NEG_INF;
            }
        }
        float rm0 = NEG_INF, rm1 = NEG_INF;
        #pragma unroll
        for (int j = 0; j < 8; j++) {
            rm0 = fmaxf(rm0, fmaxf(S[j][0], S[j][1]));
            rm1 = fmaxf(rm1, fmaxf(S[j][2], S[j][3]));
        }
        rm0 = fmaxf(rm0, __shfl_xor_sync(0xffffffffu, rm0, 1));
        rm0 = fmaxf(rm0, __shfl_xor_sync(0xffffffffu, rm0, 2));
        rm1 = fmaxf(rm1, __shfl_xor_sync(0xffffffffu, rm1, 1));
        rm1 = fmaxf(rm1, __shfl_xor_sync(0xffffffffu, rm1, 2));

        const float mn0 = fmaxf(mrow0, rm0);
        const float mn1 = fmaxf(mrow1, rm1);
        const float al0 = (mrow0 == NEG_INF) ? 0.f : exp2f(mrow0 - mn0);
        const float al1 = (mrow1 == NEG_INF) ? 0.f : exp2f(mrow1 - mn1);

        float ps0 = 0.f, ps1 = 0.f;
        #pragma unroll
        for (int j = 0; j < 8; j++) {
            float p;
            p = (S[j][0] == NEG_INF) ? 0.f : exp2f(S[j][0] - mn0); S[j][0] = p; ps0 += p;
            p = (S[j][1] == NEG_INF) ? 0.f : exp2f(S[j][1] - mn0); S[j][1] = p; ps0 += p;
            p = (S[j][2] == NEG_INF) ? 0.f : exp2f(S[j][2] - mn1); S[j][2] = p; ps1 += p;
            p = (S[j][3] == NEG_INF) ? 0.f : exp2f(S[j][3] - mn1); S[j][3] = p; ps1 += p;
        }
        lp0 = lp0 * al0 + ps0; mrow0 = mn0;
        lp1 = lp1 * al1 + ps1; mrow1 = mn1;
        #pragma unroll
        for (int j = 0; j < 8; j++) {
            O[j][0] *= al0; O[j][1] *= al0;
            O[j][2] *= al1; O[j][3] *= al1;
        }

        #pragma unroll
        for (int ks = 0; ks < 4; ks++) {
            uint32_t Ph[4], Pl[4];
            splitpack(S[2*ks][0],   S[2*ks][1],   Ph[0], Pl[0]);
            splitpack(S[2*ks][2],   S[2*ks][3],   Ph[1], Pl[1]);
            splitpack(S[2*ks+1][0], S[2*ks+1][1], Ph[2], Pl[2]);
            splitpack(S[2*ks+1][2], S[2*ks+1][3], Ph[3], Pl[3]);

            uint32_t Vh[8][2];
            #pragma unroll
            for (int jp = 0; jp < 4; jp++) {
                const int row = ks * 16 + (grp & 1) * 8 + rw;
                const int ch  = 2 * jp + (grp >> 1);
                uint32_t t[4];
                ldsm4t(t, stV + row * 128 + ((ch ^ (row & 7)) << 4));
                Vh[2*jp][0] = t[0]; Vh[2*jp][1] = t[1];
                Vh[2*jp+1][0] = t[2]; Vh[2*jp+1][1] = t[3];
            }
            #pragma unroll
            for (int j = 0; j < 8; j++)
                mma_f16(O[j], Ph, Vh[j]);
            #pragma unroll
            for (int j = 0; j < 8; j++)
                mma_f16(O[j], Pl, Vh[j]);
        }
        __syncthreads();
    }

    // final row-sum lane reduction
    float lrow0 = lp0, lrow1 = lp1;
    lrow0 += __shfl_xor_sync(0xffffffffu, lrow0, 1);
    lrow0 += __shfl_xor_sync(0xffffffffu, lrow0, 2);
    lrow1 += __shfl_xor_sync(0xffffffffu, lrow1, 1);
    lrow1 += __shfl_xor_sync(0xffffffffu, lrow1, 2);

    const float ri0 = (lrow0 > 0.f) ? 1.f / lrow0 : 0.f;
    const float ri1 = (lrow1 > 0.f) ? 1.f / lrow1 : 0.f;
    const int m0 = b * 1024 + qt * 64 + qr0;
    const int m1 = m0 + 8;
    #pragma unroll
    for (int j = 0; j < 8; j++) {
        const int col = h * 64 + j * 8 + c0;
        const int chunk = col >> 5, wc = col & 31;
        uint32_t hi, lo;
        splitpack(O[j][0] * ri0, O[j][1] * ri0, hi, lo);
        size_t base = ((size_t)m0 * 32 + chunk) * 64 + wc;
        *(uint32_t*)(outp + base)      = hi;
        *(uint32_t*)(outp + base + 32) = lo;
        splitpack(O[j][2] * ri1, O[j][3] * ri1, hi, lo);
        base = ((size_t)m1 * 32 + chunk) * 64 + wc;
        *(uint32_t*)(outp + base)      = hi;
        *(uint32_t*)(outp + base + 32) = lo;
    }
}

// ---------------------------------------------------------------------------
extern "C" void kernel_launch(void* const* d_in, const int* in_sizes, int n_in,
                              void* d_out, int out_size)
{
    const float*     x   = (const float*)d_in[0];
    const long long* ids = (const long long*)d_in[1];
    const float*     Wq  = (const float*)d_in[2];
    const float*     bq  = (const float*)d_in[3];
    const float*     Wk  = (const float*)d_in[4];
    const float*     bk  = (const float*)d_in[5];
    const float*     Wv  = (const float*)d_in[6];
    const float*     bv  = (const float*)d_in[7];
    const float*     Wo  = (const float*)d_in[8];
    const float*     bo  = (const float*)d_in[9];
    float* out = (float*)d_out;

    __half *xc, *ac, *wqc, *wkc, *wvc, *woc, *qh, *ql, *kh, *vh;
    float* vb;
    cudaGetSymbolAddress((void**)&xc,  g_xc);
    cudaGetSymbolAddress((void**)&ac,  g_ac);
    cudaGetSymbolAddress((void**)&wqc, g_wqc);
    cudaGetSymbolAddress((void**)&wkc, g_wkc);
    cudaGetSymbolAddress((void**)&wvc, g_wvc);
    cudaGetSymbolAddress((void**)&woc, g_woc);
    cudaGetSymbolAddress((void**)&qh,  g_qh);
    cudaGetSymbolAddress((void**)&ql,  g_ql);
    cudaGetSymbolAddress((void**)&kh,  g_kh);
    cudaGetSymbolAddress((void**)&vh,  g_vh);
    cudaGetSymbolAddress((void**)&vb,  g_vb);

    const int gemm_smem  = 3 * GSTAGE;            // 72KB -> 2 CTAs/SM
    const int flash_smem = 20480 + 2 * FSTAGE;    // 52KB -> 4 CTAs/SM
    cudaFuncSetAttribute(gemm_qkv, cudaFuncAttributeMaxDynamicSharedMemorySize, gemm_smem);
    cudaFuncSetAttribute(gemm_ao,  cudaFuncAttributeMaxDynamicSharedMemorySize, gemm_smem);
    cudaFuncSetAttribute(flash_f16, cudaFuncAttributeMaxDynamicSharedMemorySize, flash_smem);

    convert_split<<<(MROWS*128)/256, 256>>>(x, xc, MROWS);
    convert_w4<<<dim3((DD*128)/256, 4), 256>>>(Wq, Wk, Wv, Wo, wqc, wkc, wvc, woc);
    pad_mask<<<MROWS/256, 256>>>(ids, vb);

    gemm_qkv<<<dim3(8, 64, 3), 256, gemm_smem>>>(xc, wqc, wkc, wvc, bq, bk, bv,
                                                 qh, ql, kh, vh);

    flash_f16<<<dim3(16, 16, 8), 128, flash_smem>>>(qh, ql, kh, vh, vb, ac);

    gemm_ao<<<dim3(8, 64), 256, gemm_smem>>>(ac, woc, bo, out);
}

// round 12
// speedup vs baseline: 1.0486x; 1.0486x over previous
#include <cuda_runtime.h>
#include <cuda_fp16.h>
#include <math.h>
#include <stdint.h>

// Problem constants
#define BB   8
#define SS   1024
#define DD   1024
#define HH   16
#define HD   64
#define MROWS (BB*SS)   // 8192
#define NCHUNK 32       // K / 32
#define NEG_INF (-INFINITY)
#define QSCALE 0.18033688011112042f   // 0.125 * log2(e)

// Scratch (allocation-free rule: __device__ globals)
__device__ __half g_xc [MROWS*2048];
__device__ __half g_ac [MROWS*2048];
__device__ __half g_wqc[DD*2048];
__device__ __half g_wkc[DD*2048];
__device__ __half g_wvc[DD*2048];
__device__ __half g_woc[DD*2048];
__device__ __half g_qh[MROWS*DD], g_ql[MROWS*DD];
__device__ __half g_kh[MROWS*DD];
__device__ __half g_vh[MROWS*DD];
__device__ float g_vb[MROWS];

// ---------------------------------------------------------------------------
// PTX helpers
// ---------------------------------------------------------------------------
__device__ __forceinline__ uint32_t smem_u32(const void* p) {
    uint32_t a;
    asm("{ .reg .u64 t; cvta.to.shared.u64 t, %1; cvt.u32.u64 %0, t; }" : "=r"(a) : "l"(p));
    return a;
}
__device__ __forceinline__ void cp16(uint32_t dst, const void* src) {
    asm volatile("cp.async.cg.shared.global [%0], [%1], 16;" :: "r"(dst), "l"(src));
}
#define CP_COMMIT() asm volatile("cp.async.commit_group;" ::: "memory")
#define CP_WAIT(n)  asm volatile("cp.async.wait_group %0;" :: "n"(n) : "memory")

__device__ __forceinline__ void ldsm4(uint32_t* r, uint32_t addr) {
    asm volatile("ldmatrix.sync.aligned.m8n8.x4.shared.b16 {%0,%1,%2,%3}, [%4];"
                 : "=r"(r[0]), "=r"(r[1]), "=r"(r[2]), "=r"(r[3]) : "r"(addr));
}
__device__ __forceinline__ void ldsm4t(uint32_t* r, uint32_t addr) {
    asm volatile("ldmatrix.sync.aligned.m8n8.x4.trans.shared.b16 {%0,%1,%2,%3}, [%4];"
                 : "=r"(r[0]), "=r"(r[1]), "=r"(r[2]), "=r"(r[3]) : "r"(addr));
}
__device__ __forceinline__ void mma_f16(float* d, const uint32_t* a, const uint32_t* b) {
    asm volatile("mma.sync.aligned.m16n8k16.row.col.f32.f16.f16.f32 "
                 "{%0,%1,%2,%3}, {%4,%5,%6,%7}, {%8,%9}, {%0,%1,%2,%3};"
                 : "+f"(d[0]), "+f"(d[1]), "+f"(d[2]), "+f"(d[3])
                 : "r"(a[0]), "r"(a[1]), "r"(a[2]), "r"(a[3]), "r"(b[0]), "r"(b[1]));
}
__device__ __forceinline__ uint32_t pack2h(float x, float y) {
    __half2 h2 = __floats2half2_rn(x, y);
    uint32_t u; memcpy(&u, &h2, 4); return u;
}
__device__ __forceinline__ void splitpack(float x, float y, uint32_t& hi, uint32_t& lo) {
    __half2 h2 = __floats2half2_rn(x, y);
    memcpy(&hi, &h2, 4);
    lo = pack2h(x - __low2float(h2), y - __high2float(h2));
}

// ---------------------------------------------------------------------------
// Split-convert: fp32 [rows][1024] -> packed fp16 [rows][32][hi32|lo32]
// ---------------------------------------------------------------------------
__device__ __forceinline__ void convert_body(
    const float* __restrict__ in, __half* __restrict__ out, int g)
{
    const int row  = g >> 7;
    const int w    = g & 127;
    const int kc   = w >> 2;
    const int part = w & 3;

    const float* src = in + (size_t)row * 1024 + kc * 32 + part * 8;
    float4 f0 = *(const float4*)(src);
    float4 f1 = *(const float4*)(src + 4);
    const float xs[8] = {f0.x, f0.y, f0.z, f0.w, f1.x, f1.y, f1.z, f1.w};

    alignas(16) __half h[8];
    alignas(16) __half l[8];
    #pragma unroll
    for (int e = 0; e < 8; e++) {
        h[e] = __float2half_rn(xs[e]);
        l[e] = __float2half_rn(xs[e] - __half2float(h[e]));
    }
    __half* dst = out + ((size_t)row * 32 + kc) * 64 + part * 8;
    *(uint4*)(dst)      = *(const uint4*)h;
    *(uint4*)(dst + 32) = *(const uint4*)l;
}

__global__ __launch_bounds__(256) void convert_split(
    const float* __restrict__ in, __half* __restrict__ out, int rows)
{
    const int g = blockIdx.x * 256 + threadIdx.x;
    if (g < rows * 128) convert_body(in, out, g);
}

__global__ __launch_bounds__(256) void convert_w4(
    const float* __restrict__ w0, const float* __restrict__ w1,
    const float* __restrict__ w2, const float* __restrict__ w3,
    __half* o0, __half* o1, __half* o2, __half* o3)
{
    const int g = blockIdx.x * 256 + threadIdx.x;
    const int z = blockIdx.y;
    const float* in    = (z == 0) ? w0 : (z == 1) ? w1 : (z == 2) ? w2 : w3;
    __half* out        = (z == 0) ? o0 : (z == 1) ? o1 : (z == 2) ? o2 : o3;
    if (g < DD * 128) convert_body(in, out, g);
}

__global__ void pad_mask(const long long* __restrict__ ids, float* __restrict__ vb) {
    int i = blockIdx.x * 256 + threadIdx.x;
    if (i < MROWS) vb[i] = (ids[i] != 1LL) ? 0.f : NEG_INF;
}

// ---------------------------------------------------------------------------
// GEMM core: fp16 2-term split via mma.sync. C = (Ah+Al)*Wh^T (+bias)*scale.
// ldsm swizzle addresses factored into hoisted row_base + xor_term adds.
// Pipeline tail fixed: final iteration waits for ALL groups (the chunk-31
// group can otherwise still be in flight when read -> nondeterminism).
// ---------------------------------------------------------------------------
#define GSTAGE 24576

__device__ __forceinline__ void gemm_core(
    const __half* __restrict__ Ap, const __half* __restrict__ Bp,
    const float* __restrict__ bias, float* __restrict__ outf,
    __half* __restrict__ oh, __half* __restrict__ ol,
    float scale, int mode, char* dsm, int bm, int bn)
{
    const uint32_t smem_base = smem_u32(dsm);
    const int tid  = threadIdx.x;
    const int wid  = tid >> 5;
    const int lane = tid & 31;
    const int wm = (wid & 3) << 5;
    const int wn = (wid >> 2) << 6;

    uint32_t rowA[2], xA[4], rowB[4], xB[2];
    {
        const int l7 = lane & 7, l15 = lane & 15, hi16 = lane >> 4;
        #pragma unroll
        for (int f = 0; f < 2; f++) rowA[f] = (uint32_t)(wm + f * 16 + l15) * 128u;
        #pragma unroll
        for (int ks = 0; ks < 2; ks++) {
            xA[ks*2+0] = (uint32_t)(((ks*2 + hi16) ^ l7) << 4);
            xA[ks*2+1] = (uint32_t)(((ks*2 + 4 + hi16) ^ l7) << 4);
            xB[ks]     = (uint32_t)(((ks*2 + hi16) ^ ((lane >> 1) & 3)) << 4);
        }
        #pragma unroll
        for (int p = 0; p < 4; p++) rowB[p] = (uint32_t)(wn + p * 16 + l15) * 64u;
    }

    auto load_stage = [&](int kc, int s) {
        const uint32_t sA = smem_base + s * GSTAGE;
        const uint32_t sB = sA + 16384;
        #pragma unroll
        for (int v = 0; v < 4; v++) {
            const int cid = v * 256 + tid;
            const int row = cid >> 3;
            const int c   = cid & 7;
            cp16(sA + row * 128 + ((c ^ (row & 7)) << 4),
                 Ap + (((size_t)(bm + row) * 32 + kc) << 6) + c * 8);
        }
        #pragma unroll
        for (int v = 0; v < 2; v++) {
            const int cid = v * 256 + tid;
            const int row = cid >> 2;
            const int c   = cid & 3;
            cp16(sB + row * 64 + ((c ^ ((row >> 1) & 3)) << 4),
                 Bp + (((size_t)(bn + row) * 32 + kc) << 6) + c * 8);
        }
        CP_COMMIT();
    };

    float acc[2][8][4];
    #pragma unroll
    for (int i = 0; i < 2; i++)
        #pragma unroll
        for (int j = 0; j < 8; j++)
            #pragma unroll
            for (int e = 0; e < 4; e++) acc[i][j][e] = 0.f;

    load_stage(0, 0);
    load_stage(1, 1);

    int stage = 0;
    for (int i = 0; i < NCHUNK; i++) {
        if (i == NCHUNK - 1) { CP_WAIT(0); }   // last chunk's group must be done
        else                 { CP_WAIT(1); }
        __syncthreads();

        const uint32_t sA = smem_base + stage * GSTAGE;
        const uint32_t sB = sA + 16384;

        #pragma unroll
        for (int ks = 0; ks < 2; ks++) {
            uint32_t Ah[2][4], Al[2][4];
            #pragma unroll
            for (int f = 0; f < 2; f++) {
                ldsm4(Ah[f], sA + rowA[f] + xA[ks*2+0]);
                ldsm4(Al[f], sA + rowA[f] + xA[ks*2+1]);
            }
            #pragma unroll
            for (int ph = 0; ph < 2; ph++) {
                uint32_t Bh[4][2];
                #pragma unroll
                for (int pp = 0; pp < 2; pp++) {
                    const int p = ph * 2 + pp;
                    uint32_t q[4];
                    ldsm4(q, sB + rowB[p] + xB[ks]);
                    Bh[2*pp][0] = q[0]; Bh[2*pp][1] = q[2];
                    Bh[2*pp+1][0] = q[1]; Bh[2*pp+1][1] = q[3];
                }
                #pragma unroll
                for (int f = 0; f < 2; f++)
                    #pragma unroll
                    for (int jj = 0; jj < 4; jj++) {
                        float* a = acc[f][ph * 4 + jj];
                        mma_f16(a, Ah[f], Bh[jj]);
                        mma_f16(a, Al[f], Bh[jj]);
                    }
            }
        }

        if (i + 2 < NCHUNK) {
            int ws = stage + 2; if (ws >= 3) ws -= 3;
            load_stage(i + 2, ws);
        }
        if (++stage == 3) stage = 0;
    }

    #pragma unroll
    for (int f = 0; f < 2; f++) {
        #pragma unroll
        for (int j = 0; j < 8; j++) {
            const int col = bn + wn + j * 8 + ((lane & 3) << 1);
            const float b0 = bias[col], b1 = bias[col + 1];
            #pragma unroll
            for (int half = 0; half < 2; half++) {
                const int m = bm + wm + f * 16 + (lane >> 2) + half * 8;
                float2 o;
                o.x = (acc[f][j][half * 2 + 0] + b0) * scale;
                o.y = (acc[f][j][half * 2 + 1] + b1) * scale;
                if (mode == 0) {
                    *(float2*)(outf + (size_t)m * DD + col) = o;
                } else {
                    const int b_ = m >> 10, s_ = m & 1023;
                    const int h_ = col >> 6, d_ = col & 63;
                    const size_t idx = ((size_t)(b_ * HH + h_) * SS + s_) * HD + d_;
                    uint32_t hi, lo;
                    splitpack(o.x, o.y, hi, lo);
                    *(uint32_t*)(oh + idx) = hi;
                    if (ol) *(uint32_t*)(ol + idx) = lo;
                }
            }
        }
    }
}

__global__ __launch_bounds__(256, 2) void gemm_qkv(
    const __half* __restrict__ xc,
    const __half* __restrict__ wq, const __half* __restrict__ wk,
    const __half* __restrict__ wv,
    const float* __restrict__ bq, const float* __restrict__ bk,
    const float* __restrict__ bv,
    __half* qh, __half* ql, __half* kh, __half* vh)
{
    extern __shared__ char dsm[];
    const int z = blockIdx.z;
    const __half* Bp   = (z == 0) ? wq : (z == 1) ? wk : wv;
    const float* bias  = (z == 0) ? bq : (z == 1) ? bk : bv;
    __half* oh         = (z == 0) ? qh : (z == 1) ? kh : vh;
    __half* ol         = (z == 0) ? ql : nullptr;
    const float scale  = (z == 0) ? QSCALE : 1.f;
    gemm_core(xc, Bp, bias, nullptr, oh, ol, scale, 1, dsm,
              blockIdx.y << 7, blockIdx.x << 7);
}

__global__ __launch_bounds__(256, 2) void gemm_ao(
    const __half* __restrict__ ac, const __half* __restrict__ woc,
    const float* __restrict__ bo, float* __restrict__ out)
{
    extern __shared__ char dsm[];
    gemm_core(ac, woc, bo, out, nullptr, nullptr, 1.f, 0, dsm,
              blockIdx.y << 7, blockIdx.x << 7);
}

// ---------------------------------------------------------------------------
// Flash attention, fp16 mma.sync. Q split (2 planes); K,V,P single plane.
// 64-row q tiles, 128 threads/4 warps, grid (16,16,8), exp2-domain softmax.
// (Tail is already exact here: last iteration uses CP_WAIT(0).)
// ---------------------------------------------------------------------------
#define FSTAGE 16384

__global__ __launch_bounds__(128) void flash_f16(
    const __half* __restrict__ qh, const __half* __restrict__ ql,
    const __half* __restrict__ kh, const __half* __restrict__ vh,
    const float* __restrict__ vb, __half* __restrict__ outp)
{
    extern __shared__ char dsm[];
    const uint32_t sb = smem_u32(dsm);

    const int tid  = threadIdx.x;
    const int wid  = tid >> 5;
    const int lane = tid & 31;
    const int qt = blockIdx.x, h = blockIdx.y, b = blockIdx.z;
    const size_t bhrow = ((size_t)b * HH + h) * SS;

    const uint32_t sQh = sb, sQl = sb + 8192;
    const uint32_t sVB = sb + 16384;
    const float* svp = (const float*)(dsm + 16384);
    const uint32_t stage_base = sb + 20480;

    auto ldplane = [&](uint32_t dst, const __half* src) {
        #pragma unroll
        for (int v = 0; v < 4; v++) {
            const int cid = v * 128 + tid;
            const int row = cid >> 3, c = cid & 7;
            cp16(dst + row * 128 + ((c ^ (row & 7)) << 4),
                 src + (size_t)row * 64 + c * 8);
        }
    };
    auto load_stage = [&](int kt, int s) {
        const uint32_t st = stage_base + (uint32_t)s * FSTAGE;
        const size_t ro = (bhrow + (size_t)kt * 64) * 64;
        ldplane(st,        kh + ro);
        ldplane(st + 8192, vh + ro);
        CP_COMMIT();
    };

    {
        const size_t qo = (bhrow + (size_t)qt * 64) * 64;
        ldplane(sQh, qh + qo);
        ldplane(sQl, ql + qo);
        #pragma unroll
        for (int v = 0; v < 2; v++) {
            const int cid = v * 128 + tid;
            cp16(sVB + cid * 16, vb + (size_t)b * SS + cid * 4);
        }
        CP_COMMIT();
    }
    load_stage(0, 0);

    const int grp = lane >> 3, rw = lane & 7;
    const int c0  = (lane & 3) << 1;
    const int qr0 = wid * 16 + (lane >> 2);
    const int qr1 = qr0 + 8;

    uint32_t rowK[4], xK[4], rowV[4], xV[4];
    #pragma unroll
    for (int i = 0; i < 4; i++) {
        rowK[i] = (uint32_t)(i * 16 + (grp >> 1) * 8 + rw) * 128u;  // jp
        xK[i]   = (uint32_t)(((2 * i + (grp & 1)) ^ rw) << 4);      // ks
        rowV[i] = (uint32_t)(i * 16 + (grp & 1) * 8 + rw) * 128u;   // ks
        xV[i]   = (uint32_t)(((2 * i + (grp >> 1)) ^ rw) << 4);     // jp
    }

    uint32_t Qh[4][4], Ql[4][4];
    float O[8][4];
    #pragma unroll
    for (int j = 0; j < 8; j++)
        #pragma unroll
        for (int e = 0; e < 4; e++) O[j][e] = 0.f;
    float mrow0 = NEG_INF, mrow1 = NEG_INF;
    float lp0 = 0.f, lp1 = 0.f;

    for (int kt = 0; kt <= qt; kt++) {
        const int s = kt & 1;
        if (kt < qt) { load_stage(kt + 1, s ^ 1); CP_WAIT(1); }
        else         { CP_WAIT(0); }
        __syncthreads();

        if (kt == 0) {
            #pragma unroll
            for (int ks = 0; ks < 4; ks++) {
                const int row = wid * 16 + (grp & 1) * 8 + rw;
                const int ch  = 2 * ks + (grp >> 1);
                const uint32_t off = row * 128 + ((ch ^ rw) << 4);
                ldsm4(Qh[ks], sQh + off);
                ldsm4(Ql[ks], sQl + off);
            }
        }

        const uint32_t stK = stage_base + (uint32_t)s * FSTAGE;
        const uint32_t stV = stK + 8192;

        float S[8][4];
        #pragma unroll
        for (int j = 0; j < 8; j++)
            #pragma unroll
            for (int e = 0; e < 4; e++) S[j][e] = 0.f;

        #pragma unroll
        for (int ks = 0; ks < 4; ks++) {
            uint32_t Bh[8][2];
            #pragma unroll
            for (int jp = 0; jp < 4; jp++) {
                uint32_t t[4];
                ldsm4(t, stK + rowK[jp] + xK[ks]);
                Bh[2*jp][0] = t[0]; Bh[2*jp][1] = t[1];
                Bh[2*jp+1][0] = t[2]; Bh[2*jp+1][1] = t[3];
            }
            #pragma unroll
            for (int j = 0; j < 8; j++) {
                mma_f16(S[j], Qh[ks], Bh[j]);
                mma_f16(S[j], Ql[ks], Bh[j]);
            }
        }

        #pragma unroll
        for (int j = 0; j < 8; j++) {
            const int k0 = j * 8 + c0, k1 = k0 + 1;
            const float p0 = svp[kt * 64 + k0];
            const float p1 = svp[kt * 64 + k1];
            S[j][0] += p0; S[j][1] += p1; S[j][2] += p0; S[j][3] += p1;
            if (kt == qt) {
                if (k0 > qr0) S[j][0] = NEG_INF;
                if (k1 > qr0) S[j][1] = NEG_INF;
                if (k0 > qr1) S[j][2] = NEG_INF;
                if (k1 > qr1) S[j][3] = NEG_INF;
            }
        }
        float rm0 = NEG_INF, rm1 = NEG_INF;
        #pragma unroll
        for (int j = 0; j < 8; j++) {
            rm0 = fmaxf(rm0, fmaxf(S[j][0], S[j][1]));
            rm1 = fmaxf(rm1, fmaxf(S[j][2], S[j][3]));
        }
        rm0 = fmaxf(rm0, __shfl_xor_sync(0xffffffffu, rm0, 1));
        rm0 = fmaxf(rm0, __shfl_xor_sync(0xffffffffu, rm0, 2));
        rm1 = fmaxf(rm1, __shfl_xor_sync(0xffffffffu, rm1, 1));
        rm1 = fmaxf(rm1, __shfl_xor_sync(0xffffffffu, rm1, 2));

        const float mn0 = fmaxf(mrow0, rm0);
        const float mn1 = fmaxf(mrow1, rm1);
        const float al0 = (mrow0 == NEG_INF) ? 0.f : exp2f(mrow0 - mn0);
        const float al1 = (mrow1 == NEG_INF) ? 0.f : exp2f(mrow1 - mn1);

        float ps0 = 0.f, ps1 = 0.f;
        #pragma unroll
        for (int j = 0; j < 8; j++) {
            float p;
            p = (S[j][0] == NEG_INF) ? 0.f : exp2f(S[j][0] - mn0); S[j][0] = p; ps0 += p;
            p = (S[j][1] == NEG_INF) ? 0.f : exp2f(S[j][1] - mn0); S[j][1] = p; ps0 += p;
            p = (S[j][2] == NEG_INF) ? 0.f : exp2f(S[j][2] - mn1); S[j][2] = p; ps1 += p;
            p = (S[j][3] == NEG_INF) ? 0.f : exp2f(S[j][3] - mn1); S[j][3] = p; ps1 += p;
        }
        lp0 = lp0 * al0 + ps0; mrow0 = mn0;
        lp1 = lp1 * al1 + ps1; mrow1 = mn1;
        #pragma unroll
        for (int j = 0; j < 8; j++) {
            O[j][0] *= al0; O[j][1] *= al0;
            O[j][2] *= al1; O[j][3] *= al1;
        }

        #pragma unroll
        for (int ks = 0; ks < 4; ks++) {
            uint32_t Ph[4];
            Ph[0] = pack2h(S[2*ks][0],   S[2*ks][1]);
            Ph[1] = pack2h(S[2*ks][2],   S[2*ks][3]);
            Ph[2] = pack2h(S[2*ks+1][0], S[2*ks+1][1]);
            Ph[3] = pack2h(S[2*ks+1][2], S[2*ks+1][3]);

            uint32_t Vh[8][2];
            #pragma unroll
            for (int jp = 0; jp < 4; jp++) {
                uint32_t t[4];
                ldsm4t(t, stV + rowV[ks] + xV[jp]);
                Vh[2*jp][0] = t[0]; Vh[2*jp][1] = t[1];
                Vh[2*jp+1][0] = t[2]; Vh[2*jp+1][1] = t[3];
            }
            #pragma unroll
            for (int j = 0; j < 8; j++)
                mma_f16(O[j], Ph, Vh[j]);
        }
        __syncthreads();
    }

    float lrow0 = lp0, lrow1 = lp1;
    lrow0 += __shfl_xor_sync(0xffffffffu, lrow0, 1);
    lrow0 += __shfl_xor_sync(0xffffffffu, lrow0, 2);
    lrow1 += __shfl_xor_sync(0xffffffffu, lrow1, 1);
    lrow1 += __shfl_xor_sync(0xffffffffu, lrow1, 2);

    const float ri0 = (lrow0 > 0.f) ? 1.f / lrow0 : 0.f;
    const float ri1 = (lrow1 > 0.f) ? 1.f / lrow1 : 0.f;
    const int m0 = b * 1024 + qt * 64 + qr0;
    const int m1 = m0 + 8;
    #pragma unroll
    for (int j = 0; j < 8; j++) {
        const int col = h * 64 + j * 8 + c0;
        const int chunk = col >> 5, wc = col & 31;
        uint32_t hi, lo;
        splitpack(O[j][0] * ri0, O[j][1] * ri0, hi, lo);
        size_t base = ((size_t)m0 * 32 + chunk) * 64 + wc;
        *(uint32_t*)(outp + base)      = hi;
        *(uint32_t*)(outp + base + 32) = lo;
        splitpack(O[j][2] * ri1, O[j][3] * ri1, hi, lo);
        base = ((size_t)m1 * 32 + chunk) * 64 + wc;
        *(uint32_t*)(outp + base)      = hi;
        *(uint32_t*)(outp + base + 32) = lo;
    }
}

// ---------------------------------------------------------------------------
extern "C" void kernel_launch(void* const* d_in, const int* in_sizes, int n_in,
                              void* d_out, int out_size)
{
    const float*     x   = (const float*)d_in[0];
    const long long* ids = (const long long*)d_in[1];
    const float*     Wq  = (const float*)d_in[2];
    const float*     bq  = (const float*)d_in[3];
    const float*     Wk  = (const float*)d_in[4];
    const float*     bk  = (const float*)d_in[5];
    const float*     Wv  = (const float*)d_in[6];
    const float*     bv  = (const float*)d_in[7];
    const float*     Wo  = (const float*)d_in[8];
    const float*     bo  = (const float*)d_in[9];
    float* out = (float*)d_out;

    __half *xc, *ac, *wqc, *wkc, *wvc, *woc, *qh, *ql, *kh, *vh;
    float* vb;
    cudaGetSymbolAddress((void**)&xc,  g_xc);
    cudaGetSymbolAddress((void**)&ac,  g_ac);
    cudaGetSymbolAddress((void**)&wqc, g_wqc);
    cudaGetSymbolAddress((void**)&wkc, g_wkc);
    cudaGetSymbolAddress((void**)&wvc, g_wvc);
    cudaGetSymbolAddress((void**)&woc, g_woc);
    cudaGetSymbolAddress((void**)&qh,  g_qh);
    cudaGetSymbolAddress((void**)&ql,  g_ql);
    cudaGetSymbolAddress((void**)&kh,  g_kh);
    cudaGetSymbolAddress((void**)&vh,  g_vh);
    cudaGetSymbolAddress((void**)&vb,  g_vb);

    const int gemm_smem  = 3 * GSTAGE;            // 72KB -> 2 CTAs/SM
    const int flash_smem = 20480 + 2 * FSTAGE;    // 52KB -> 4 CTAs/SM
    cudaFuncSetAttribute(gemm_qkv, cudaFuncAttributeMaxDynamicSharedMemorySize, gemm_smem);
    cudaFuncSetAttribute(gemm_ao,  cudaFuncAttributeMaxDynamicSharedMemorySize, gemm_smem);
    cudaFuncSetAttribute(flash_f16, cudaFuncAttributeMaxDynamicSharedMemorySize, flash_smem);

    convert_split<<<(MROWS*128)/256, 256>>>(x, xc, MROWS);
    convert_w4<<<dim3((DD*128)/256, 4), 256>>>(Wq, Wk, Wv, Wo, wqc, wkc, wvc, woc);
    pad_mask<<<MROWS/256, 256>>>(ids, vb);

    gemm_qkv<<<dim3(8, 64, 3), 256, gemm_smem>>>(xc, wqc, wkc, wvc, bq, bk, bv,
                                                 qh, ql, kh, vh);

    flash_f16<<<dim3(16, 16, 8), 128, flash_smem>>>(qh, ql, kh, vh, vb, ac);

    gemm_ao<<<dim3(8, 64), 256, gemm_smem>>>(ac, woc, bo, out);
}

// round 13
// speedup vs baseline: 1.0972x; 1.0464x over previous
#include <cuda_runtime.h>
#include <cuda_fp16.h>
#include <math.h>
#include <stdint.h>

// Problem constants
#define BB   8
#define SS   1024
#define DD   1024
#define HH   16
#define HD   64
#define MROWS (BB*SS)   // 8192
#define NCHUNK 32       // K / 32
#define NEG_INF (-INFINITY)
#define QSCALE 0.18033688011112042f   // 0.125 * log2(e)

// Scratch (allocation-free rule: __device__ globals)
__device__ __half g_xc [MROWS*2048];
__device__ __half g_ac [MROWS*2048];
__device__ __half g_wqc[DD*2048];
__device__ __half g_wkc[DD*2048];
__device__ __half g_wvc[DD*2048];
__device__ __half g_woc[DD*2048];
__device__ __half g_qh[MROWS*DD], g_ql[MROWS*DD];
__device__ __half g_kh[MROWS*DD];
__device__ __half g_vh[MROWS*DD];
__device__ float g_vb[MROWS];

// ---------------------------------------------------------------------------
// PTX helpers
// ---------------------------------------------------------------------------
__device__ __forceinline__ uint32_t smem_u32(const void* p) {
    uint32_t a;
    asm("{ .reg .u64 t; cvta.to.shared.u64 t, %1; cvt.u32.u64 %0, t; }" : "=r"(a) : "l"(p));
    return a;
}
__device__ __forceinline__ void cp16(uint32_t dst, const void* src) {
    asm volatile("cp.async.cg.shared.global [%0], [%1], 16;" :: "r"(dst), "l"(src));
}
#define CP_COMMIT() asm volatile("cp.async.commit_group;" ::: "memory")
#define CP_WAIT(n)  asm volatile("cp.async.wait_group %0;" :: "n"(n) : "memory")

__device__ __forceinline__ void ldsm4(uint32_t* r, uint32_t addr) {
    asm volatile("ldmatrix.sync.aligned.m8n8.x4.shared.b16 {%0,%1,%2,%3}, [%4];"
                 : "=r"(r[0]), "=r"(r[1]), "=r"(r[2]), "=r"(r[3]) : "r"(addr));
}
__device__ __forceinline__ void ldsm4t(uint32_t* r, uint32_t addr) {
    asm volatile("ldmatrix.sync.aligned.m8n8.x4.trans.shared.b16 {%0,%1,%2,%3}, [%4];"
                 : "=r"(r[0]), "=r"(r[1]), "=r"(r[2]), "=r"(r[3]) : "r"(addr));
}
__device__ __forceinline__ void mma_f16(float* d, const uint32_t* a, const uint32_t* b) {
    asm volatile("mma.sync.aligned.m16n8k16.row.col.f32.f16.f16.f32 "
                 "{%0,%1,%2,%3}, {%4,%5,%6,%7}, {%8,%9}, {%0,%1,%2,%3};"
                 : "+f"(d[0]), "+f"(d[1]), "+f"(d[2]), "+f"(d[3])
                 : "r"(a[0]), "r"(a[1]), "r"(a[2]), "r"(a[3]), "r"(b[0]), "r"(b[1]));
}
__device__ __forceinline__ uint32_t pack2h(float x, float y) {
    __half2 h2 = __floats2half2_rn(x, y);
    uint32_t u; memcpy(&u, &h2, 4); return u;
}
__device__ __forceinline__ void splitpack(float x, float y, uint32_t& hi, uint32_t& lo) {
    __half2 h2 = __floats2half2_rn(x, y);
    memcpy(&hi, &h2, 4);
    lo = pack2h(x - __low2float(h2), y - __high2float(h2));
}

// ---------------------------------------------------------------------------
// Split-convert: fp32 [rows][1024] -> packed fp16 [rows][32][hi32|lo32]
// ---------------------------------------------------------------------------
__device__ __forceinline__ void convert_body(
    const float* __restrict__ in, __half* __restrict__ out, int g)
{
    const int row  = g >> 7;
    const int w    = g & 127;
    const int kc   = w >> 2;
    const int part = w & 3;

    const float* src = in + (size_t)row * 1024 + kc * 32 + part * 8;
    float4 f0 = *(const float4*)(src);
    float4 f1 = *(const float4*)(src + 4);
    const float xs[8] = {f0.x, f0.y, f0.z, f0.w, f1.x, f1.y, f1.z, f1.w};

    alignas(16) __half h[8];
    alignas(16) __half l[8];
    #pragma unroll
    for (int e = 0; e < 8; e++) {
        h[e] = __float2half_rn(xs[e]);
        l[e] = __float2half_rn(xs[e] - __half2float(h[e]));
    }
    __half* dst = out + ((size_t)row * 32 + kc) * 64 + part * 8;
    *(uint4*)(dst)      = *(const uint4*)h;
    *(uint4*)(dst + 32) = *(const uint4*)l;
}

__global__ __launch_bounds__(256) void convert_split(
    const float* __restrict__ in, __half* __restrict__ out, int rows)
{
    const int g = blockIdx.x * 256 + threadIdx.x;
    if (g < rows * 128) convert_body(in, out, g);
}

__global__ __launch_bounds__(256) void convert_w4(
    const float* __restrict__ w0, const float* __restrict__ w1,
    const float* __restrict__ w2, const float* __restrict__ w3,
    __half* o0, __half* o1, __half* o2, __half* o3)
{
    const int g = blockIdx.x * 256 + threadIdx.x;
    const int z = blockIdx.y;
    const float* in    = (z == 0) ? w0 : (z == 1) ? w1 : (z == 2) ? w2 : w3;
    __half* out        = (z == 0) ? o0 : (z == 1) ? o1 : (z == 2) ? o2 : o3;
    if (g < DD * 128) convert_body(in, out, g);
}

__global__ void pad_mask(const long long* __restrict__ ids, float* __restrict__ vb) {
    int i = blockIdx.x * 256 + threadIdx.x;
    if (i < MROWS) vb[i] = (ids[i] != 1LL) ? 0.f : NEG_INF;
}

// ---------------------------------------------------------------------------
// GEMM core: fp16 2-term split via mma.sync. C = (Ah+Al)*Wh^T (+bias)*scale.
// 64x128 tile, 128 threads (4 warps, warp tile 32x64), 3-stage pipeline
// (16KB/stage) -> 4 independent CTAs/SM. Barriers sync only 4 warps; the
// other resident CTAs fill the drain. Exact tail wait (no race).
// ---------------------------------------------------------------------------
#define GSTAGE 16384

__device__ __forceinline__ void gemm_core(
    const __half* __restrict__ Ap, const __half* __restrict__ Bp,
    const float* __restrict__ bias, float* __restrict__ outf,
    __half* __restrict__ oh, __half* __restrict__ ol,
    float scale, int mode, char* dsm, int bm, int bn)
{
    const uint32_t smem_base = smem_u32(dsm);
    const int tid  = threadIdx.x;
    const int wid  = tid >> 5;
    const int lane = tid & 31;
    const int wm = (wid & 1) << 5;    // 0 or 32
    const int wn = (wid >> 1) << 6;   // 0 or 64

    uint32_t rowA[2], xA[4], rowB[4], xB[2];
    {
        const int l7 = lane & 7, l15 = lane & 15, hi16 = lane >> 4;
        #pragma unroll
        for (int f = 0; f < 2; f++) rowA[f] = (uint32_t)(wm + f * 16 + l15) * 128u;
        #pragma unroll
        for (int ks = 0; ks < 2; ks++) {
            xA[ks*2+0] = (uint32_t)(((ks*2 + hi16) ^ l7) << 4);
            xA[ks*2+1] = (uint32_t)(((ks*2 + 4 + hi16) ^ l7) << 4);
            xB[ks]     = (uint32_t)(((ks*2 + hi16) ^ ((lane >> 1) & 3)) << 4);
        }
        #pragma unroll
        for (int p = 0; p < 4; p++) rowB[p] = (uint32_t)(wn + p * 16 + l15) * 64u;
    }

    auto load_stage = [&](int kc, int s) {
        const uint32_t sA = smem_base + s * GSTAGE;
        const uint32_t sB = sA + 8192;
        // A: 64 rows x 128B (hi+lo), 512 cp16 / 128 threads
        #pragma unroll
        for (int v = 0; v < 4; v++) {
            const int cid = v * 128 + tid;
            const int row = cid >> 3;
            const int c   = cid & 7;
            cp16(sA + row * 128 + ((c ^ (row & 7)) << 4),
                 Ap + (((size_t)(bm + row) * 32 + kc) << 6) + c * 8);
        }
        // B: 128 rows x 64B (hi only), 512 cp16 / 128 threads
        #pragma unroll
        for (int v = 0; v < 4; v++) {
            const int cid = v * 128 + tid;
            const int row = cid >> 2;
            const int c   = cid & 3;
            cp16(sB + row * 64 + ((c ^ ((row >> 1) & 3)) << 4),
                 Bp + (((size_t)(bn + row) * 32 + kc) << 6) + c * 8);
        }
        CP_COMMIT();
    };

    float acc[2][8][4];
    #pragma unroll
    for (int i = 0; i < 2; i++)
        #pragma unroll
        for (int j = 0; j < 8; j++)
            #pragma unroll
            for (int e = 0; e < 4; e++) acc[i][j][e] = 0.f;

    load_stage(0, 0);
    load_stage(1, 1);

    int stage = 0;
    for (int i = 0; i < NCHUNK; i++) {
        if (i == NCHUNK - 1) { CP_WAIT(0); }   // exact tail wait
        else                 { CP_WAIT(1); }
        __syncthreads();

        const uint32_t sA = smem_base + stage * GSTAGE;
        const uint32_t sB = sA + 8192;

        #pragma unroll
        for (int ks = 0; ks < 2; ks++) {
            uint32_t Ah[2][4], Al[2][4];
            #pragma unroll
            for (int f = 0; f < 2; f++) {
                ldsm4(Ah[f], sA + rowA[f] + xA[ks*2+0]);
                ldsm4(Al[f], sA + rowA[f] + xA[ks*2+1]);
            }
            #pragma unroll
            for (int ph = 0; ph < 2; ph++) {
                uint32_t Bh[4][2];
                #pragma unroll
                for (int pp = 0; pp < 2; pp++) {
                    const int p = ph * 2 + pp;
                    uint32_t q[4];
                    ldsm4(q, sB + rowB[p] + xB[ks]);
                    Bh[2*pp][0] = q[0]; Bh[2*pp][1] = q[2];
                    Bh[2*pp+1][0] = q[1]; Bh[2*pp+1][1] = q[3];
                }
                #pragma unroll
                for (int f = 0; f < 2; f++)
                    #pragma unroll
                    for (int jj = 0; jj < 4; jj++) {
                        float* a = acc[f][ph * 4 + jj];
                        mma_f16(a, Ah[f], Bh[jj]);
                        mma_f16(a, Al[f], Bh[jj]);
                    }
            }
        }

        if (i + 2 < NCHUNK) {
            int ws = stage + 2; if (ws >= 3) ws -= 3;
            load_stage(i + 2, ws);
        }
        if (++stage == 3) stage = 0;
    }

    #pragma unroll
    for (int f = 0; f < 2; f++) {
        #pragma unroll
        for (int j = 0; j < 8; j++) {
            const int col = bn + wn + j * 8 + ((lane & 3) << 1);
            const float b0 = bias[col], b1 = bias[col + 1];
            #pragma unroll
            for (int half = 0; half < 2; half++) {
                const int m = bm + wm + f * 16 + (lane >> 2) + half * 8;
                float2 o;
                o.x = (acc[f][j][half * 2 + 0] + b0) * scale;
                o.y = (acc[f][j][half * 2 + 1] + b1) * scale;
                if (mode == 0) {
                    *(float2*)(outf + (size_t)m * DD + col) = o;
                } else {
                    const int b_ = m >> 10, s_ = m & 1023;
                    const int h_ = col >> 6, d_ = col & 63;
                    const size_t idx = ((size_t)(b_ * HH + h_) * SS + s_) * HD + d_;
                    uint32_t hi, lo;
                    splitpack(o.x, o.y, hi, lo);
                    *(uint32_t*)(oh + idx) = hi;
                    if (ol) *(uint32_t*)(ol + idx) = lo;
                }
            }
        }
    }
}

// Fused QKV projections: grid (8, 128, 3). Q gets split planes; K,V hi only.
__global__ __launch_bounds__(128, 4) void gemm_qkv(
    const __half* __restrict__ xc,
    const __half* __restrict__ wq, const __half* __restrict__ wk,
    const __half* __restrict__ wv,
    const float* __restrict__ bq, const float* __restrict__ bk,
    const float* __restrict__ bv,
    __half* qh, __half* ql, __half* kh, __half* vh)
{
    extern __shared__ char dsm[];
    const int z = blockIdx.z;
    const __half* Bp   = (z == 0) ? wq : (z == 1) ? wk : wv;
    const float* bias  = (z == 0) ? bq : (z == 1) ? bk : bv;
    __half* oh         = (z == 0) ? qh : (z == 1) ? kh : vh;
    __half* ol         = (z == 0) ? ql : nullptr;
    const float scale  = (z == 0) ? QSCALE : 1.f;
    gemm_core(xc, Bp, bias, nullptr, oh, ol, scale, 1, dsm,
              blockIdx.y << 6, blockIdx.x << 7);
}

__global__ __launch_bounds__(128, 4) void gemm_ao(
    const __half* __restrict__ ac, const __half* __restrict__ woc,
    const float* __restrict__ bo, float* __restrict__ out)
{
    extern __shared__ char dsm[];
    gemm_core(ac, woc, bo, out, nullptr, nullptr, 1.f, 0, dsm,
              blockIdx.y << 6, blockIdx.x << 7);
}

// ---------------------------------------------------------------------------
// Flash attention, fp16 mma.sync. Q split (2 planes); K,V,P single plane.
// 64-row q tiles, 128 threads/4 warps, grid (16,16,8), exp2-domain softmax.
// ---------------------------------------------------------------------------
#define FSTAGE 16384

__global__ __launch_bounds__(128) void flash_f16(
    const __half* __restrict__ qh, const __half* __restrict__ ql,
    const __half* __restrict__ kh, const __half* __restrict__ vh,
    const float* __restrict__ vb, __half* __restrict__ outp)
{
    extern __shared__ char dsm[];
    const uint32_t sb = smem_u32(dsm);

    const int tid  = threadIdx.x;
    const int wid  = tid >> 5;
    const int lane = tid & 31;
    const int qt = blockIdx.x, h = blockIdx.y, b = blockIdx.z;
    const size_t bhrow = ((size_t)b * HH + h) * SS;

    const uint32_t sQh = sb, sQl = sb + 8192;
    const uint32_t sVB = sb + 16384;
    const float* svp = (const float*)(dsm + 16384);
    const uint32_t stage_base = sb + 20480;

    auto ldplane = [&](uint32_t dst, const __half* src) {
        #pragma unroll
        for (int v = 0; v < 4; v++) {
            const int cid = v * 128 + tid;
            const int row = cid >> 3, c = cid & 7;
            cp16(dst + row * 128 + ((c ^ (row & 7)) << 4),
                 src + (size_t)row * 64 + c * 8);
        }
    };
    auto load_stage = [&](int kt, int s) {
        const uint32_t st = stage_base + (uint32_t)s * FSTAGE;
        const size_t ro = (bhrow + (size_t)kt * 64) * 64;
        ldplane(st,        kh + ro);
        ldplane(st + 8192, vh + ro);
        CP_COMMIT();
    };

    {
        const size_t qo = (bhrow + (size_t)qt * 64) * 64;
        ldplane(sQh, qh + qo);
        ldplane(sQl, ql + qo);
        #pragma unroll
        for (int v = 0; v < 2; v++) {
            const int cid = v * 128 + tid;
            cp16(sVB + cid * 16, vb + (size_t)b * SS + cid * 4);
        }
        CP_COMMIT();
    }
    load_stage(0, 0);

    const int grp = lane >> 3, rw = lane & 7;
    const int c0  = (lane & 3) << 1;
    const int qr0 = wid * 16 + (lane >> 2);
    const int qr1 = qr0 + 8;

    uint32_t rowK[4], xK[4], rowV[4], xV[4];
    #pragma unroll
    for (int i = 0; i < 4; i++) {
        rowK[i] = (uint32_t)(i * 16 + (grp >> 1) * 8 + rw) * 128u;
        xK[i]   = (uint32_t)(((2 * i + (grp & 1)) ^ rw) << 4);
        rowV[i] = (uint32_t)(i * 16 + (grp & 1) * 8 + rw) * 128u;
        xV[i]   = (uint32_t)(((2 * i + (grp >> 1)) ^ rw) << 4);
    }

    uint32_t Qh[4][4], Ql[4][4];
    float O[8][4];
    #pragma unroll
    for (int j = 0; j < 8; j++)
        #pragma unroll
        for (int e = 0; e < 4; e++) O[j][e] = 0.f;
    float mrow0 = NEG_INF, mrow1 = NEG_INF;
    float lp0 = 0.f, lp1 = 0.f;

    for (int kt = 0; kt <= qt; kt++) {
        const int s = kt & 1;
        if (kt < qt) { load_stage(kt + 1, s ^ 1); CP_WAIT(1); }
        else         { CP_WAIT(0); }
        __syncthreads();

        if (kt == 0) {
            #pragma unroll
            for (int ks = 0; ks < 4; ks++) {
                const int row = wid * 16 + (grp & 1) * 8 + rw;
                const int ch  = 2 * ks + (grp >> 1);
                const uint32_t off = row * 128 + ((ch ^ rw) << 4);
                ldsm4(Qh[ks], sQh + off);
                ldsm4(Ql[ks], sQl + off);
            }
        }

        const uint32_t stK = stage_base + (uint32_t)s * FSTAGE;
        const uint32_t stV = stK + 8192;

        float S[8][4];
        #pragma unroll
        for (int j = 0; j < 8; j++)
            #pragma unroll
            for (int e = 0; e < 4; e++) S[j][e] = 0.f;

        #pragma unroll
        for (int ks = 0; ks < 4; ks++) {
            uint32_t Bh[8][2];
            #pragma unroll
            for (int jp = 0; jp < 4; jp++) {
                uint32_t t[4];
                ldsm4(t, stK + rowK[jp] + xK[ks]);
                Bh[2*jp][0] = t[0]; Bh[2*jp][1] = t[1];
                Bh[2*jp+1][0] = t[2]; Bh[2*jp+1][1] = t[3];
            }
            #pragma unroll
            for (int j = 0; j < 8; j++) {
                mma_f16(S[j], Qh[ks], Bh[j]);
                mma_f16(S[j], Ql[ks], Bh[j]);
            }
        }

        #pragma unroll
        for (int j = 0; j < 8; j++) {
            const int k0 = j * 8 + c0, k1 = k0 + 1;
            const float p0 = svp[kt * 64 + k0];
            const float p1 = svp[kt * 64 + k1];
            S[j][0] += p0; S[j][1] += p1; S[j][2] += p0; S[j][3] += p1;
            if (kt == qt) {
                if (k0 > qr0) S[j][0] = NEG_INF;
                if (k1 > qr0) S[j][1] = NEG_INF;
                if (k0 > qr1) S[j][2] = NEG_INF;
                if (k1 > qr1) S[j][3] = NEG_INF;
            }
        }
        float rm0 = NEG_INF, rm1 = NEG_INF;
        #pragma unroll
        for (int j = 0; j < 8; j++) {
            rm0 = fmaxf(rm0, fmaxf(S[j][0], S[j][1]));
            rm1 = fmaxf(rm1, fmaxf(S[j][2], S[j][3]));
        }
        rm0 = fmaxf(rm0, __shfl_xor_sync(0xffffffffu, rm0, 1));
        rm0 = fmaxf(rm0, __shfl_xor_sync(0xffffffffu, rm0, 2));
        rm1 = fmaxf(rm1, __shfl_xor_sync(0xffffffffu, rm1, 1));
        rm1 = fmaxf(rm1, __shfl_xor_sync(0xffffffffu, rm1, 2));

        const float mn0 = fmaxf(mrow0, rm0);
        const float mn1 = fmaxf(mrow1, rm1);
        const float al0 = (mrow0 == NEG_INF) ? 0.f : exp2f(mrow0 - mn0);
        const float al1 = (mrow1 == NEG_INF) ? 0.f : exp2f(mrow1 - mn1);

        float ps0 = 0.f, ps1 = 0.f;
        #pragma unroll
        for (int j = 0; j < 8; j++) {
            float p;
            p = (S[j][0] == NEG_INF) ? 0.f : exp2f(S[j][0] - mn0); S[j][0] = p; ps0 += p;
            p = (S[j][1] == NEG_INF) ? 0.f : exp2f(S[j][1] - mn0); S[j][1] = p; ps0 += p;
            p = (S[j][2] == NEG_INF) ? 0.f : exp2f(S[j][2] - mn1); S[j][2] = p; ps1 += p;
            p = (S[j][3] == NEG_INF) ? 0.f : exp2f(S[j][3] - mn1); S[j][3] = p; ps1 += p;
        }
        lp0 = lp0 * al0 + ps0; mrow0 = mn0;
        lp1 = lp1 * al1 + ps1; mrow1 = mn1;
        #pragma unroll
        for (int j = 0; j < 8; j++) {
            O[j][0] *= al0; O[j][1] *= al0;
            O[j][2] *= al1; O[j][3] *= al1;
        }

        #pragma unroll
        for (int ks = 0; ks < 4; ks++) {
            uint32_t Ph[4];
            Ph[0] = pack2h(S[2*ks][0],   S[2*ks][1]);
            Ph[1] = pack2h(S[2*ks][2],   S[2*ks][3]);
            Ph[2] = pack2h(S[2*ks+1][0], S[2*ks+1][1]);
            Ph[3] = pack2h(S[2*ks+1][2], S[2*ks+1][3]);

            uint32_t Vh[8][2];
            #pragma unroll
            for (int jp = 0; jp < 4; jp++) {
                uint32_t t[4];
                ldsm4t(t, stV + rowV[ks] + xV[jp]);
                Vh[2*jp][0] = t[0]; Vh[2*jp][1] = t[1];
                Vh[2*jp+1][0] = t[2]; Vh[2*jp+1][1] = t[3];
            }
            #pragma unroll
            for (int j = 0; j < 8; j++)
                mma_f16(O[j], Ph, Vh[j]);
        }
        __syncthreads();
    }

    float lrow0 = lp0, lrow1 = lp1;
    lrow0 += __shfl_xor_sync(0xffffffffu, lrow0, 1);
    lrow0 += __shfl_xor_sync(0xffffffffu, lrow0, 2);
    lrow1 += __shfl_xor_sync(0xffffffffu, lrow1, 1);
    lrow1 += __shfl_xor_sync(0xffffffffu, lrow1, 2);

    const float ri0 = (lrow0 > 0.f) ? 1.f / lrow0 : 0.f;
    const float ri1 = (lrow1 > 0.f) ? 1.f / lrow1 : 0.f;
    const int m0 = b * 1024 + qt * 64 + qr0;
    const int m1 = m0 + 8;
    #pragma unroll
    for (int j = 0; j < 8; j++) {
        const int col = h * 64 + j * 8 + c0;
        const int chunk = col >> 5, wc = col & 31;
        uint32_t hi, lo;
        splitpack(O[j][0] * ri0, O[j][1] * ri0, hi, lo);
        size_t base = ((size_t)m0 * 32 + chunk) * 64 + wc;
        *(uint32_t*)(outp + base)      = hi;
        *(uint32_t*)(outp + base + 32) = lo;
        splitpack(O[j][2] * ri1, O[j][3] * ri1, hi, lo);
        base = ((size_t)m1 * 32 + chunk) * 64 + wc;
        *(uint32_t*)(outp + base)      = hi;
        *(uint32_t*)(outp + base + 32) = lo;
    }
}

// ---------------------------------------------------------------------------
extern "C" void kernel_launch(void* const* d_in, const int* in_sizes, int n_in,
                              void* d_out, int out_size)
{
    const float*     x   = (const float*)d_in[0];
    const long long* ids = (const long long*)d_in[1];
    const float*     Wq  = (const float*)d_in[2];
    const float*     bq  = (const float*)d_in[3];
    const float*     Wk  = (const float*)d_in[4];
    const float*     bk  = (const float*)d_in[5];
    const float*     Wv  = (const float*)d_in[6];
    const float*     bv  = (const float*)d_in[7];
    const float*     Wo  = (const float*)d_in[8];
    const float*     bo  = (const float*)d_in[9];
    float* out = (float*)d_out;

    __half *xc, *ac, *wqc, *wkc, *wvc, *woc, *qh, *ql, *kh, *vh;
    float* vb;
    cudaGetSymbolAddress((void**)&xc,  g_xc);
    cudaGetSymbolAddress((void**)&ac,  g_ac);
    cudaGetSymbolAddress((void**)&wqc, g_wqc);
    cudaGetSymbolAddress((void**)&wkc, g_wkc);
    cudaGetSymbolAddress((void**)&wvc, g_wvc);
    cudaGetSymbolAddress((void**)&woc, g_woc);
    cudaGetSymbolAddress((void**)&qh,  g_qh);
    cudaGetSymbolAddress((void**)&ql,  g_ql);
    cudaGetSymbolAddress((void**)&kh,  g_kh);
    cudaGetSymbolAddress((void**)&vh,  g_vh);
    cudaGetSymbolAddress((void**)&vb,  g_vb);

    const int gemm_smem  = 3 * GSTAGE;            // 48KB -> 4 CTAs/SM
    const int flash_smem = 20480 + 2 * FSTAGE;    // 52KB
    cudaFuncSetAttribute(gemm_qkv, cudaFuncAttributeMaxDynamicSharedMemorySize, gemm_smem);
    cudaFuncSetAttribute(gemm_ao,  cudaFuncAttributeMaxDynamicSharedMemorySize, gemm_smem);
    cudaFuncSetAttribute(flash_f16, cudaFuncAttributeMaxDynamicSharedMemorySize, flash_smem);

    convert_split<<<(MROWS*128)/256, 256>>>(x, xc, MROWS);
    convert_w4<<<dim3((DD*128)/256, 4), 256>>>(Wq, Wk, Wv, Wo, wqc, wkc, wvc, woc);
    pad_mask<<<MROWS/256, 256>>>(ids, vb);

    gemm_qkv<<<dim3(8, 128, 3), 128, gemm_smem>>>(xc, wqc, wkc, wvc, bq, bk, bv,
                                                  qh, ql, kh, vh);

    flash_f16<<<dim3(16, 16, 8), 128, flash_smem>>>(qh, ql, kh, vh, vb, ac);

    gemm_ao<<<dim3(8, 128), 128, gemm_smem>>>(ac, woc, bo, out);
}

// round 14
// speedup vs baseline: 1.2028x; 1.0962x over previous
#include <cuda_runtime.h>
#include <cuda_fp16.h>
#include <math.h>
#include <stdint.h>

// Problem constants
#define BB   8
#define SS   1024
#define DD   1024
#define HH   16
#define HD   64
#define MROWS (BB*SS)   // 8192
#define NCHUNK 32       // K / 32
#define NEG_INF (-INFINITY)
#define QSCALE 0.18033688011112042f   // 0.125 * log2(e)

// Scratch (allocation-free rule: __device__ globals)
__device__ __half g_xc [MROWS*2048];
__device__ __half g_ac [MROWS*1024];   // attention out, SINGLE fp16 plane [row][1024]
__device__ __half g_wqc[DD*2048];
__device__ __half g_wkc[DD*2048];
__device__ __half g_wvc[DD*2048];
__device__ __half g_woc[DD*2048];
__device__ __half g_qh[MROWS*DD], g_ql[MROWS*DD];
__device__ __half g_kh[MROWS*DD];
__device__ __half g_vh[MROWS*DD];
__device__ float g_vb[MROWS];

// ---------------------------------------------------------------------------
// PTX helpers
// ---------------------------------------------------------------------------
__device__ __forceinline__ uint32_t smem_u32(const void* p) {
    uint32_t a;
    asm("{ .reg .u64 t; cvta.to.shared.u64 t, %1; cvt.u32.u64 %0, t; }" : "=r"(a) : "l"(p));
    return a;
}
__device__ __forceinline__ void cp16(uint32_t dst, const void* src) {
    asm volatile("cp.async.cg.shared.global [%0], [%1], 16;" :: "r"(dst), "l"(src));
}
#define CP_COMMIT() asm volatile("cp.async.commit_group;" ::: "memory")
#define CP_WAIT(n)  asm volatile("cp.async.wait_group %0;" :: "n"(n) : "memory")

__device__ __forceinline__ void ldsm4(uint32_t* r, uint32_t addr) {
    asm volatile("ldmatrix.sync.aligned.m8n8.x4.shared.b16 {%0,%1,%2,%3}, [%4];"
                 : "=r"(r[0]), "=r"(r[1]), "=r"(r[2]), "=r"(r[3]) : "r"(addr));
}
__device__ __forceinline__ void ldsm4t(uint32_t* r, uint32_t addr) {
    asm volatile("ldmatrix.sync.aligned.m8n8.x4.trans.shared.b16 {%0,%1,%2,%3}, [%4];"
                 : "=r"(r[0]), "=r"(r[1]), "=r"(r[2]), "=r"(r[3]) : "r"(addr));
}
__device__ __forceinline__ void mma_f16(float* d, const uint32_t* a, const uint32_t* b) {
    asm volatile("mma.sync.aligned.m16n8k16.row.col.f32.f16.f16.f32 "
                 "{%0,%1,%2,%3}, {%4,%5,%6,%7}, {%8,%9}, {%0,%1,%2,%3};"
                 : "+f"(d[0]), "+f"(d[1]), "+f"(d[2]), "+f"(d[3])
                 : "r"(a[0]), "r"(a[1]), "r"(a[2]), "r"(a[3]), "r"(b[0]), "r"(b[1]));
}
__device__ __forceinline__ uint32_t pack2h(float x, float y) {
    __half2 h2 = __floats2half2_rn(x, y);
    uint32_t u; memcpy(&u, &h2, 4); return u;
}
__device__ __forceinline__ void splitpack(float x, float y, uint32_t& hi, uint32_t& lo) {
    __half2 h2 = __floats2half2_rn(x, y);
    memcpy(&hi, &h2, 4);
    lo = pack2h(x - __low2float(h2), y - __high2float(h2));
}

// ---------------------------------------------------------------------------
// Split-convert: fp32 [rows][1024] -> packed fp16 [rows][32][hi32|lo32]
// ---------------------------------------------------------------------------
__device__ __forceinline__ void convert_body(
    const float* __restrict__ in, __half* __restrict__ out, int g)
{
    const int row  = g >> 7;
    const int w    = g & 127;
    const int kc   = w >> 2;
    const int part = w & 3;

    const float* src = in + (size_t)row * 1024 + kc * 32 + part * 8;
    float4 f0 = *(const float4*)(src);
    float4 f1 = *(const float4*)(src + 4);
    const float xs[8] = {f0.x, f0.y, f0.z, f0.w, f1.x, f1.y, f1.z, f1.w};

    alignas(16) __half h[8];
    alignas(16) __half l[8];
    #pragma unroll
    for (int e = 0; e < 8; e++) {
        h[e] = __float2half_rn(xs[e]);
        l[e] = __float2half_rn(xs[e] - __half2float(h[e]));
    }
    __half* dst = out + ((size_t)row * 32 + kc) * 64 + part * 8;
    *(uint4*)(dst)      = *(const uint4*)h;
    *(uint4*)(dst + 32) = *(const uint4*)l;
}

__global__ __launch_bounds__(256) void convert_split(
    const float* __restrict__ in, __half* __restrict__ out, int rows)
{
    const int g = blockIdx.x * 256 + threadIdx.x;
    if (g < rows * 128) convert_body(in, out, g);
}

__global__ __launch_bounds__(256) void convert_w4(
    const float* __restrict__ w0, const float* __restrict__ w1,
    const float* __restrict__ w2, const float* __restrict__ w3,
    __half* o0, __half* o1, __half* o2, __half* o3)
{
    const int g = blockIdx.x * 256 + threadIdx.x;
    const int z = blockIdx.y;
    const float* in    = (z == 0) ? w0 : (z == 1) ? w1 : (z == 2) ? w2 : w3;
    __half* out        = (z == 0) ? o0 : (z == 1) ? o1 : (z == 2) ? o2 : o3;
    if (g < DD * 128) convert_body(in, out, g);
}

__global__ void pad_mask(const long long* __restrict__ ids, float* __restrict__ vb) {
    int i = blockIdx.x * 256 + threadIdx.x;
    if (i < MROWS) vb[i] = (ids[i] != 1LL) ? 0.f : NEG_INF;
}

// ---------------------------------------------------------------------------
// GEMM core (2-term A): C = (Ah+Al)*Wh^T (+bias)*scale. 64x128 tile, 128 thr,
// 3-stage pipeline (16KB/stage) -> 4 CTAs/SM. Exact tail wait.
// ---------------------------------------------------------------------------
#define GSTAGE 16384

__device__ __forceinline__ void gemm_core(
    const __half* __restrict__ Ap, const __half* __restrict__ Bp,
    const float* __restrict__ bias,
    __half* __restrict__ oh, __half* __restrict__ ol,
    float scale, char* dsm, int bm, int bn)
{
    const uint32_t smem_base = smem_u32(dsm);
    const int tid  = threadIdx.x;
    const int wid  = tid >> 5;
    const int lane = tid & 31;
    const int wm = (wid & 1) << 5;
    const int wn = (wid >> 1) << 6;

    uint32_t rowA[2], xA[4], rowB[4], xB[2];
    {
        const int l7 = lane & 7, l15 = lane & 15, hi16 = lane >> 4;
        #pragma unroll
        for (int f = 0; f < 2; f++) rowA[f] = (uint32_t)(wm + f * 16 + l15) * 128u;
        #pragma unroll
        for (int ks = 0; ks < 2; ks++) {
            xA[ks*2+0] = (uint32_t)(((ks*2 + hi16) ^ l7) << 4);
            xA[ks*2+1] = (uint32_t)(((ks*2 + 4 + hi16) ^ l7) << 4);
            xB[ks]     = (uint32_t)(((ks*2 + hi16) ^ ((lane >> 1) & 3)) << 4);
        }
        #pragma unroll
        for (int p = 0; p < 4; p++) rowB[p] = (uint32_t)(wn + p * 16 + l15) * 64u;
    }

    auto load_stage = [&](int kc, int s) {
        const uint32_t sA = smem_base + s * GSTAGE;
        const uint32_t sB = sA + 8192;
        #pragma unroll
        for (int v = 0; v < 4; v++) {
            const int cid = v * 128 + tid;
            const int row = cid >> 3;
            const int c   = cid & 7;
            cp16(sA + row * 128 + ((c ^ (row & 7)) << 4),
                 Ap + (((size_t)(bm + row) * 32 + kc) << 6) + c * 8);
        }
        #pragma unroll
        for (int v = 0; v < 4; v++) {
            const int cid = v * 128 + tid;
            const int row = cid >> 2;
            const int c   = cid & 3;
            cp16(sB + row * 64 + ((c ^ ((row >> 1) & 3)) << 4),
                 Bp + (((size_t)(bn + row) * 32 + kc) << 6) + c * 8);
        }
        CP_COMMIT();
    };

    float acc[2][8][4];
    #pragma unroll
    for (int i = 0; i < 2; i++)
        #pragma unroll
        for (int j = 0; j < 8; j++)
            #pragma unroll
            for (int e = 0; e < 4; e++) acc[i][j][e] = 0.f;

    load_stage(0, 0);
    load_stage(1, 1);

    int stage = 0;
    for (int i = 0; i < NCHUNK; i++) {
        if (i == NCHUNK - 1) { CP_WAIT(0); }
        else                 { CP_WAIT(1); }
        __syncthreads();

        const uint32_t sA = smem_base + stage * GSTAGE;
        const uint32_t sB = sA + 8192;

        #pragma unroll
        for (int ks = 0; ks < 2; ks++) {
            uint32_t Ah[2][4], Al[2][4];
            #pragma unroll
            for (int f = 0; f < 2; f++) {
                ldsm4(Ah[f], sA + rowA[f] + xA[ks*2+0]);
                ldsm4(Al[f], sA + rowA[f] + xA[ks*2+1]);
            }
            #pragma unroll
            for (int ph = 0; ph < 2; ph++) {
                uint32_t Bh[4][2];
                #pragma unroll
                for (int pp = 0; pp < 2; pp++) {
                    const int p = ph * 2 + pp;
                    uint32_t q[4];
                    ldsm4(q, sB + rowB[p] + xB[ks]);
                    Bh[2*pp][0] = q[0]; Bh[2*pp][1] = q[2];
                    Bh[2*pp+1][0] = q[1]; Bh[2*pp+1][1] = q[3];
                }
                #pragma unroll
                for (int f = 0; f < 2; f++)
                    #pragma unroll
                    for (int jj = 0; jj < 4; jj++) {
                        float* a = acc[f][ph * 4 + jj];
                        mma_f16(a, Ah[f], Bh[jj]);
                        mma_f16(a, Al[f], Bh[jj]);
                    }
            }
        }

        if (i + 2 < NCHUNK) {
            int ws = stage + 2; if (ws >= 3) ws -= 3;
            load_stage(i + 2, ws);
        }
        if (++stage == 3) stage = 0;
    }

    #pragma unroll
    for (int f = 0; f < 2; f++) {
        #pragma unroll
        for (int j = 0; j < 8; j++) {
            const int col = bn + wn + j * 8 + ((lane & 3) << 1);
            const float b0 = bias[col], b1 = bias[col + 1];
            #pragma unroll
            for (int half = 0; half < 2; half++) {
                const int m = bm + wm + f * 16 + (lane >> 2) + half * 8;
                float2 o;
                o.x = (acc[f][j][half * 2 + 0] + b0) * scale;
                o.y = (acc[f][j][half * 2 + 1] + b1) * scale;
                const int b_ = m >> 10, s_ = m & 1023;
                const int h_ = col >> 6, d_ = col & 63;
                const size_t idx = ((size_t)(b_ * HH + h_) * SS + s_) * HD + d_;
                uint32_t hi, lo;
                splitpack(o.x, o.y, hi, lo);
                *(uint32_t*)(oh + idx) = hi;
                if (ol) *(uint32_t*)(ol + idx) = lo;
            }
        }
    }
}

// Fused QKV projections: grid (8, 128, 3). Q gets split planes; K,V hi only.
__global__ __launch_bounds__(128, 4) void gemm_qkv(
    const __half* __restrict__ xc,
    const __half* __restrict__ wq, const __half* __restrict__ wk,
    const __half* __restrict__ wv,
    const float* __restrict__ bq, const float* __restrict__ bk,
    const float* __restrict__ bv,
    __half* qh, __half* ql, __half* kh, __half* vh)
{
    extern __shared__ char dsm[];
    const int z = blockIdx.z;
    const __half* Bp   = (z == 0) ? wq : (z == 1) ? wk : wv;
    const float* bias  = (z == 0) ? bq : (z == 1) ? bk : bv;
    __half* oh         = (z == 0) ? qh : (z == 1) ? kh : vh;
    __half* ol         = (z == 0) ? ql : nullptr;
    const float scale  = (z == 0) ? QSCALE : 1.f;
    gemm_core(xc, Bp, bias, oh, ol, scale, dsm,
              blockIdx.y << 6, blockIdx.x << 7);
}

// ---------------------------------------------------------------------------
// Output projection, 1-term A (att rounded to fp16): out = att*Wo_hi^T + bo.
// A single plane [row][1024] fp16 -> 64B/chunk rows, same layout as B.
// Stage = A 4KB + B 8KB = 12KB; 3 stages = 36KB -> 4 CTAs/SM. Half the MMAs.
// ---------------------------------------------------------------------------
#define GSTAGE1 12288

__global__ __launch_bounds__(128, 4) void gemm_ao(
    const __half* __restrict__ Ap, const __half* __restrict__ Bp,
    const float* __restrict__ bias, float* __restrict__ outf)
{
    extern __shared__ char dsm[];
    const uint32_t smem_base = smem_u32(dsm);
    const int tid  = threadIdx.x;
    const int wid  = tid >> 5;
    const int lane = tid & 31;
    const int bm = blockIdx.y << 6;
    const int bn = blockIdx.x << 7;
    const int wm = (wid & 1) << 5;
    const int wn = (wid >> 1) << 6;

    uint32_t rowA[2], rowB[4], xAB[2];
    {
        const int l15 = lane & 15, hi16 = lane >> 4;
        #pragma unroll
        for (int f = 0; f < 2; f++) rowA[f] = (uint32_t)(wm + f * 16 + l15) * 64u;
        #pragma unroll
        for (int ks = 0; ks < 2; ks++)
            xAB[ks] = (uint32_t)(((ks*2 + hi16) ^ ((lane >> 1) & 3)) << 4);
        #pragma unroll
        for (int p = 0; p < 4; p++) rowB[p] = (uint32_t)(wn + p * 16 + l15) * 64u;
    }

    auto load_stage = [&](int kc, int s) {
        const uint32_t sA = smem_base + s * GSTAGE1;
        const uint32_t sB = sA + 4096;
        // A: 64 rows x 64B (single plane), 256 cp16
        #pragma unroll
        for (int v = 0; v < 2; v++) {
            const int cid = v * 128 + tid;
            const int row = cid >> 2;
            const int c   = cid & 3;
            cp16(sA + row * 64 + ((c ^ ((row >> 1) & 3)) << 4),
                 Ap + ((size_t)(bm + row) << 10) + kc * 32 + c * 8);
        }
        // B: 128 rows x 64B (hi plane), 512 cp16
        #pragma unroll
        for (int v = 0; v < 4; v++) {
            const int cid = v * 128 + tid;
            const int row = cid >> 2;
            const int c   = cid & 3;
            cp16(sB + row * 64 + ((c ^ ((row >> 1) & 3)) << 4),
                 Bp + (((size_t)(bn + row) * 32 + kc) << 6) + c * 8);
        }
        CP_COMMIT();
    };

    float acc[2][8][4];
    #pragma unroll
    for (int i = 0; i < 2; i++)
        #pragma unroll
        for (int j = 0; j < 8; j++)
            #pragma unroll
            for (int e = 0; e < 4; e++) acc[i][j][e] = 0.f;

    load_stage(0, 0);
    load_stage(1, 1);

    int stage = 0;
    for (int i = 0; i < NCHUNK; i++) {
        if (i == NCHUNK - 1) { CP_WAIT(0); }
        else                 { CP_WAIT(1); }
        __syncthreads();

        const uint32_t sA = smem_base + stage * GSTAGE1;
        const uint32_t sB = sA + 4096;

        #pragma unroll
        for (int ks = 0; ks < 2; ks++) {
            uint32_t Ah[2][4];
            #pragma unroll
            for (int f = 0; f < 2; f++)
                ldsm4(Ah[f], sA + rowA[f] + xAB[ks]);
            #pragma unroll
            for (int ph = 0; ph < 2; ph++) {
                uint32_t Bh[4][2];
                #pragma unroll
                for (int pp = 0; pp < 2; pp++) {
                    const int p = ph * 2 + pp;
                    uint32_t q[4];
                    ldsm4(q, sB + rowB[p] + xAB[ks]);
                    Bh[2*pp][0] = q[0]; Bh[2*pp][1] = q[2];
                    Bh[2*pp+1][0] = q[1]; Bh[2*pp+1][1] = q[3];
                }
                #pragma unroll
                for (int f = 0; f < 2; f++)
                    #pragma unroll
                    for (int jj = 0; jj < 4; jj++)
                        mma_f16(acc[f][ph * 4 + jj], Ah[f], Bh[jj]);
            }
        }

        if (i + 2 < NCHUNK) {
            int ws = stage + 2; if (ws >= 3) ws -= 3;
            load_stage(i + 2, ws);
        }
        if (++stage == 3) stage = 0;
    }

    #pragma unroll
    for (int f = 0; f < 2; f++) {
        #pragma unroll
        for (int j = 0; j < 8; j++) {
            const int col = bn + wn + j * 8 + ((lane & 3) << 1);
            const float b0 = bias[col], b1 = bias[col + 1];
            #pragma unroll
            for (int half = 0; half < 2; half++) {
                const int m = bm + wm + f * 16 + (lane >> 2) + half * 8;
                float2 o;
                o.x = acc[f][j][half * 2 + 0] + b0;
                o.y = acc[f][j][half * 2 + 1] + b1;
                *(float2*)(outf + (size_t)m * DD + col) = o;
            }
        }
    }
}

// ---------------------------------------------------------------------------
// Flash attention, fp16 mma.sync. Q split (2 planes); K,V,P single plane.
// 64-row q tiles, 128 threads/4 warps, grid (16,16,8), exp2-domain softmax.
// Output: single fp16 plane [row][1024].
// ---------------------------------------------------------------------------
#define FSTAGE 16384

__global__ __launch_bounds__(128) void flash_f16(
    const __half* __restrict__ qh, const __half* __restrict__ ql,
    const __half* __restrict__ kh, const __half* __restrict__ vh,
    const float* __restrict__ vb, __half* __restrict__ outp)
{
    extern __shared__ char dsm[];
    const uint32_t sb = smem_u32(dsm);

    const int tid  = threadIdx.x;
    const int wid  = tid >> 5;
    const int lane = tid & 31;
    const int qt = blockIdx.x, h = blockIdx.y, b = blockIdx.z;
    const size_t bhrow = ((size_t)b * HH + h) * SS;

    const uint32_t sQh = sb, sQl = sb + 8192;
    const uint32_t sVB = sb + 16384;
    const float* svp = (const float*)(dsm + 16384);
    const uint32_t stage_base = sb + 20480;

    auto ldplane = [&](uint32_t dst, const __half* src) {
        #pragma unroll
        for (int v = 0; v < 4; v++) {
            const int cid = v * 128 + tid;
            const int row = cid >> 3, c = cid & 7;
            cp16(dst + row * 128 + ((c ^ (row & 7)) << 4),
                 src + (size_t)row * 64 + c * 8);
        }
    };
    auto load_stage = [&](int kt, int s) {
        const uint32_t st = stage_base + (uint32_t)s * FSTAGE;
        const size_t ro = (bhrow + (size_t)kt * 64) * 64;
        ldplane(st,        kh + ro);
        ldplane(st + 8192, vh + ro);
        CP_COMMIT();
    };

    {
        const size_t qo = (bhrow + (size_t)qt * 64) * 64;
        ldplane(sQh, qh + qo);
        ldplane(sQl, ql + qo);
        #pragma unroll
        for (int v = 0; v < 2; v++) {
            const int cid = v * 128 + tid;
            cp16(sVB + cid * 16, vb + (size_t)b * SS + cid * 4);
        }
        CP_COMMIT();
    }
    load_stage(0, 0);

    const int grp = lane >> 3, rw = lane & 7;
    const int c0  = (lane & 3) << 1;
    const int qr0 = wid * 16 + (lane >> 2);
    const int qr1 = qr0 + 8;

    uint32_t rowK[4], xK[4], rowV[4], xV[4];
    #pragma unroll
    for (int i = 0; i < 4; i++) {
        rowK[i] = (uint32_t)(i * 16 + (grp >> 1) * 8 + rw) * 128u;
        xK[i]   = (uint32_t)(((2 * i + (grp & 1)) ^ rw) << 4);
        rowV[i] = (uint32_t)(i * 16 + (grp & 1) * 8 + rw) * 128u;
        xV[i]   = (uint32_t)(((2 * i + (grp >> 1)) ^ rw) << 4);
    }

    uint32_t Qh[4][4], Ql[4][4];
    float O[8][4];
    #pragma unroll
    for (int j = 0; j < 8; j++)
        #pragma unroll
        for (int e = 0; e < 4; e++) O[j][e] = 0.f;
    float mrow0 = NEG_INF, mrow1 = NEG_INF;
    float lp0 = 0.f, lp1 = 0.f;

    for (int kt = 0; kt <= qt; kt++) {
        const int s = kt & 1;
        if (kt < qt) { load_stage(kt + 1, s ^ 1); CP_WAIT(1); }
        else         { CP_WAIT(0); }
        __syncthreads();

        if (kt == 0) {
            #pragma unroll
            for (int ks = 0; ks < 4; ks++) {
                const int row = wid * 16 + (grp & 1) * 8 + rw;
                const int ch  = 2 * ks + (grp >> 1);
                const uint32_t off = row * 128 + ((ch ^ rw) << 4);
                ldsm4(Qh[ks], sQh + off);
                ldsm4(Ql[ks], sQl + off);
            }
        }

        const uint32_t stK = stage_base + (uint32_t)s * FSTAGE;
        const uint32_t stV = stK + 8192;

        float S[8][4];
        #pragma unroll
        for (int j = 0; j < 8; j++)
            #pragma unroll
            for (int e = 0; e < 4; e++) S[j][e] = 0.f;

        #pragma unroll
        for (int ks = 0; ks < 4; ks++) {
            uint32_t Bh[8][2];
            #pragma unroll
            for (int jp = 0; jp < 4; jp++) {
                uint32_t t[4];
                ldsm4(t, stK + rowK[jp] + xK[ks]);
                Bh[2*jp][0] = t[0]; Bh[2*jp][1] = t[1];
                Bh[2*jp+1][0] = t[2]; Bh[2*jp+1][1] = t[3];
            }
            #pragma unroll
            for (int j = 0; j < 8; j++) {
                mma_f16(S[j], Qh[ks], Bh[j]);
                mma_f16(S[j], Ql[ks], Bh[j]);
            }
        }

        #pragma unroll
        for (int j = 0; j < 8; j++) {
            const int k0 = j * 8 + c0, k1 = k0 + 1;
            const float p0 = svp[kt * 64 + k0];
            const float p1 = svp[kt * 64 + k1];
            S[j][0] += p0; S[j][1] += p1; S[j][2] += p0; S[j][3] += p1;
            if (kt == qt) {
                if (k0 > qr0) S[j][0] = NEG_INF;
                if (k1 > qr0) S[j][1] = NEG_INF;
                if (k0 > qr1) S[j][2] = NEG_INF;
                if (k1 > qr1) S[j][3] = NEG_INF;
            }
        }
        float rm0 = NEG_INF, rm1 = NEG_INF;
        #pragma unroll
        for (int j = 0; j < 8; j++) {
            rm0 = fmaxf(rm0, fmaxf(S[j][0], S[j][1]));
            rm1 = fmaxf(rm1, fmaxf(S[j][2], S[j][3]));
        }
        rm0 = fmaxf(rm0, __shfl_xor_sync(0xffffffffu, rm0, 1));
        rm0 = fmaxf(rm0, __shfl_xor_sync(0xffffffffu, rm0, 2));
        rm1 = fmaxf(rm1, __shfl_xor_sync(0xffffffffu, rm1, 1));
        rm1 = fmaxf(rm1, __shfl_xor_sync(0xffffffffu, rm1, 2));

        const float mn0 = fmaxf(mrow0, rm0);
        const float mn1 = fmaxf(mrow1, rm1);
        const float al0 = (mrow0 == NEG_INF) ? 0.f : exp2f(mrow0 - mn0);
        const float al1 = (mrow1 == NEG_INF) ? 0.f : exp2f(mrow1 - mn1);

        float ps0 = 0.f, ps1 = 0.f;
        #pragma unroll
        for (int j = 0; j < 8; j++) {
            float p;
            p = (S[j][0] == NEG_INF) ? 0.f : exp2f(S[j][0] - mn0); S[j][0] = p; ps0 += p;
            p = (S[j][1] == NEG_INF) ? 0.f : exp2f(S[j][1] - mn0); S[j][1] = p; ps0 += p;
            p = (S[j][2] == NEG_INF) ? 0.f : exp2f(S[j][2] - mn1); S[j][2] = p; ps1 += p;
            p = (S[j][3] == NEG_INF) ? 0.f : exp2f(S[j][3] - mn1); S[j][3] = p; ps1 += p;
        }
        lp0 = lp0 * al0 + ps0; mrow0 = mn0;
        lp1 = lp1 * al1 + ps1; mrow1 = mn1;
        #pragma unroll
        for (int j = 0; j < 8; j++) {
            O[j][0] *= al0; O[j][1] *= al0;
            O[j][2] *= al1; O[j][3] *= al1;
        }

        #pragma unroll
        for (int ks = 0; ks < 4; ks++) {
            uint32_t Ph[4];
            Ph[0] = pack2h(S[2*ks][0],   S[2*ks][1]);
            Ph[1] = pack2h(S[2*ks][2],   S[2*ks][3]);
            Ph[2] = pack2h(S[2*ks+1][0], S[2*ks+1][1]);
            Ph[3] = pack2h(S[2*ks+1][2], S[2*ks+1][3]);

            uint32_t Vh[8][2];
            #pragma unroll
            for (int jp = 0; jp < 4; jp++) {
                uint32_t t[4];
                ldsm4t(t, stV + rowV[ks] + xV[jp]);
                Vh[2*jp][0] = t[0]; Vh[2*jp][1] = t[1];
                Vh[2*jp+1][0] = t[2]; Vh[2*jp+1][1] = t[3];
            }
            #pragma unroll
            for (int j = 0; j < 8; j++)
                mma_f16(O[j], Ph, Vh[j]);
        }
        __syncthreads();
    }

    float lrow0 = lp0, lrow1 = lp1;
    lrow0 += __shfl_xor_sync(0xffffffffu, lrow0, 1);
    lrow0 += __shfl_xor_sync(0xffffffffu, lrow0, 2);
    lrow1 += __shfl_xor_sync(0xffffffffu, lrow1, 1);
    lrow1 += __shfl_xor_sync(0xffffffffu, lrow1, 2);

    const float ri0 = (lrow0 > 0.f) ? 1.f / lrow0 : 0.f;
    const float ri1 = (lrow1 > 0.f) ? 1.f / lrow1 : 0.f;
    const int m0 = b * 1024 + qt * 64 + qr0;
    const int m1 = m0 + 8;
    #pragma unroll
    for (int j = 0; j < 8; j++) {
        const int col = h * 64 + j * 8 + c0;
        *(uint32_t*)(outp + (size_t)m0 * 1024 + col) = pack2h(O[j][0] * ri0, O[j][1] * ri0);
        *(uint32_t*)(outp + (size_t)m1 * 1024 + col) = pack2h(O[j][2] * ri1, O[j][3] * ri1);
    }
}

// ---------------------------------------------------------------------------
extern "C" void kernel_launch(void* const* d_in, const int* in_sizes, int n_in,
                              void* d_out, int out_size)
{
    const float*     x   = (const float*)d_in[0];
    const long long* ids = (const long long*)d_in[1];
    const float*     Wq  = (const float*)d_in[2];
    const float*     bq  = (const float*)d_in[3];
    const float*     Wk  = (const float*)d_in[4];
    const float*     bk  = (const float*)d_in[5];
    const float*     Wv  = (const float*)d_in[6];
    const float*     bv  = (const float*)d_in[7];
    const float*     Wo  = (const float*)d_in[8];
    const float*     bo  = (const float*)d_in[9];
    float* out = (float*)d_out;

    __half *xc, *ac, *wqc, *wkc, *wvc, *woc, *qh, *ql, *kh, *vh;
    float* vb;
    cudaGetSymbolAddress((void**)&xc,  g_xc);
    cudaGetSymbolAddress((void**)&ac,  g_ac);
    cudaGetSymbolAddress((void**)&wqc, g_wqc);
    cudaGetSymbolAddress((void**)&wkc, g_wkc);
    cudaGetSymbolAddress((void**)&wvc, g_wvc);
    cudaGetSymbolAddress((void**)&woc, g_woc);
    cudaGetSymbolAddress((void**)&qh,  g_qh);
    cudaGetSymbolAddress((void**)&ql,  g_ql);
    cudaGetSymbolAddress((void**)&kh,  g_kh);
    cudaGetSymbolAddress((void**)&vh,  g_vh);
    cudaGetSymbolAddress((void**)&vb,  g_vb);

    const int gemm_smem  = 3 * GSTAGE;            // 48KB -> 4 CTAs/SM
    const int ao_smem    = 3 * GSTAGE1;           // 36KB -> 4 CTAs/SM
    const int flash_smem = 20480 + 2 * FSTAGE;    // 52KB
    cudaFuncSetAttribute(gemm_qkv, cudaFuncAttributeMaxDynamicSharedMemorySize, gemm_smem);
    cudaFuncSetAttribute(gemm_ao,  cudaFuncAttributeMaxDynamicSharedMemorySize, ao_smem);
    cudaFuncSetAttribute(flash_f16, cudaFuncAttributeMaxDynamicSharedMemorySize, flash_smem);

    convert_split<<<(MROWS*128)/256, 256>>>(x, xc, MROWS);
    convert_w4<<<dim3((DD*128)/256, 4), 256>>>(Wq, Wk, Wv, Wo, wqc, wkc, wvc, woc);
    pad_mask<<<MROWS/256, 256>>>(ids, vb);

    gemm_qkv<<<dim3(8, 128, 3), 128, gemm_smem>>>(xc, wqc, wkc, wvc, bq, bk, bv,
                                                  qh, ql, kh, vh);

    flash_f16<<<dim3(16, 16, 8), 128, flash_smem>>>(qh, ql, kh, vh, vb, ac);

    gemm_ao<<<dim3(8, 128), 128, ao_smem>>>(ac, woc, bo, out);
}

// round 15
// speedup vs baseline: 1.6184x; 1.3455x over previous
#include <cuda_runtime.h>
#include <cuda_fp16.h>
#include <math.h>
#include <stdint.h>

// Problem constants
#define BB   8
#define SS   1024
#define DD   1024
#define HH   16
#define HD   64
#define MROWS (BB*SS)   // 8192
#define NCHUNK 32       // K / 32
#define NEG_INF (-INFINITY)
#define QSCALE 0.18033688011112042f   // 0.125 * log2(e)

// Scratch (allocation-free rule: __device__ globals)
__device__ __half g_xc [MROWS*2048];   // packed x [row][32][hi32|lo32] (lo unused now)
__device__ __half g_ac [MROWS*1024];   // attention out, single fp16 plane [row][1024]
__device__ __half g_wqc[DD*2048];
__device__ __half g_wkc[DD*2048];
__device__ __half g_wvc[DD*2048];
__device__ __half g_woc[DD*2048];
__device__ __half g_qh[MROWS*DD], g_ql[MROWS*DD];
__device__ __half g_kh[MROWS*DD];
__device__ __half g_vh[MROWS*DD];
__device__ float g_vb[MROWS];

// ---------------------------------------------------------------------------
// PTX helpers
// ---------------------------------------------------------------------------
__device__ __forceinline__ uint32_t smem_u32(const void* p) {
    uint32_t a;
    asm("{ .reg .u64 t; cvta.to.shared.u64 t, %1; cvt.u32.u64 %0, t; }" : "=r"(a) : "l"(p));
    return a;
}
__device__ __forceinline__ void cp16(uint32_t dst, const void* src) {
    asm volatile("cp.async.cg.shared.global [%0], [%1], 16;" :: "r"(dst), "l"(src));
}
#define CP_COMMIT() asm volatile("cp.async.commit_group;" ::: "memory")
#define CP_WAIT(n)  asm volatile("cp.async.wait_group %0;" :: "n"(n) : "memory")

__device__ __forceinline__ void ldsm4(uint32_t* r, uint32_t addr) {
    asm volatile("ldmatrix.sync.aligned.m8n8.x4.shared.b16 {%0,%1,%2,%3}, [%4];"
                 : "=r"(r[0]), "=r"(r[1]), "=r"(r[2]), "=r"(r[3]) : "r"(addr));
}
__device__ __forceinline__ void ldsm4t(uint32_t* r, uint32_t addr) {
    asm volatile("ldmatrix.sync.aligned.m8n8.x4.trans.shared.b16 {%0,%1,%2,%3}, [%4];"
                 : "=r"(r[0]), "=r"(r[1]), "=r"(r[2]), "=r"(r[3]) : "r"(addr));
}
__device__ __forceinline__ void mma_f16(float* d, const uint32_t* a, const uint32_t* b) {
    asm volatile("mma.sync.aligned.m16n8k16.row.col.f32.f16.f16.f32 "
                 "{%0,%1,%2,%3}, {%4,%5,%6,%7}, {%8,%9}, {%0,%1,%2,%3};"
                 : "+f"(d[0]), "+f"(d[1]), "+f"(d[2]), "+f"(d[3])
                 : "r"(a[0]), "r"(a[1]), "r"(a[2]), "r"(a[3]), "r"(b[0]), "r"(b[1]));
}
__device__ __forceinline__ uint32_t pack2h(float x, float y) {
    __half2 h2 = __floats2half2_rn(x, y);
    uint32_t u; memcpy(&u, &h2, 4); return u;
}
__device__ __forceinline__ void splitpack(float x, float y, uint32_t& hi, uint32_t& lo) {
    __half2 h2 = __floats2half2_rn(x, y);
    memcpy(&hi, &h2, 4);
    lo = pack2h(x - __low2float(h2), y - __high2float(h2));
}

// ---------------------------------------------------------------------------
// Split-convert: fp32 [rows][1024] -> packed fp16 [rows][32][hi32|lo32]
// ---------------------------------------------------------------------------
__device__ __forceinline__ void convert_body(
    const float* __restrict__ in, __half* __restrict__ out, int g)
{
    const int row  = g >> 7;
    const int w    = g & 127;
    const int kc   = w >> 2;
    const int part = w & 3;

    const float* src = in + (size_t)row * 1024 + kc * 32 + part * 8;
    float4 f0 = *(const float4*)(src);
    float4 f1 = *(const float4*)(src + 4);
    const float xs[8] = {f0.x, f0.y, f0.z, f0.w, f1.x, f1.y, f1.z, f1.w};

    alignas(16) __half h[8];
    alignas(16) __half l[8];
    #pragma unroll
    for (int e = 0; e < 8; e++) {
        h[e] = __float2half_rn(xs[e]);
        l[e] = __float2half_rn(xs[e] - __half2float(h[e]));
    }
    __half* dst = out + ((size_t)row * 32 + kc) * 64 + part * 8;
    *(uint4*)(dst)      = *(const uint4*)h;
    *(uint4*)(dst + 32) = *(const uint4*)l;
}

__global__ __launch_bounds__(256) void convert_split(
    const float* __restrict__ in, __half* __restrict__ out, int rows)
{
    const int g = blockIdx.x * 256 + threadIdx.x;
    if (g < rows * 128) convert_body(in, out, g);
}

__global__ __launch_bounds__(256) void convert_w4(
    const float* __restrict__ w0, const float* __restrict__ w1,
    const float* __restrict__ w2, const float* __restrict__ w3,
    __half* o0, __half* o1, __half* o2, __half* o3)
{
    const int g = blockIdx.x * 256 + threadIdx.x;
    const int z = blockIdx.y;
    const float* in    = (z == 0) ? w0 : (z == 1) ? w1 : (z == 2) ? w2 : w3;
    __half* out        = (z == 0) ? o0 : (z == 1) ? o1 : (z == 2) ? o2 : o3;
    if (g < DD * 128) convert_body(in, out, g);
}

__global__ void pad_mask(const long long* __restrict__ ids, float* __restrict__ vb) {
    int i = blockIdx.x * 256 + threadIdx.x;
    if (i < MROWS) vb[i] = (ids[i] != 1LL) ? 0.f : NEG_INF;
}

// ---------------------------------------------------------------------------
// 1-term GEMM core: C = A_hi * W_hi^T (+bias)*scale.
// A single fp16 plane, parametrized strides (rstride halfs/row, cstride
// halfs/chunk). 64x128 tile, 128 threads, 3-stage pipeline (12KB/stage).
// mode 0: fp32 out [M,N]. mode 1: split hi/lo planes [B,H,S,HD].
// ---------------------------------------------------------------------------
#define GSTAGE1 12288

__device__ __forceinline__ void gemm1_core(
    const __half* __restrict__ Ap, int rstride, int cstride,
    const __half* __restrict__ Bp, const float* __restrict__ bias,
    float* __restrict__ outf, __half* __restrict__ oh, __half* __restrict__ ol,
    float scale, int mode, char* dsm, int bm, int bn)
{
    const uint32_t smem_base = smem_u32(dsm);
    const int tid  = threadIdx.x;
    const int wid  = tid >> 5;
    const int lane = tid & 31;
    const int wm = (wid & 1) << 5;
    const int wn = (wid >> 1) << 6;

    uint32_t rowA[2], rowB[4], xAB[2];
    {
        const int l15 = lane & 15, hi16 = lane >> 4;
        #pragma unroll
        for (int f = 0; f < 2; f++) rowA[f] = (uint32_t)(wm + f * 16 + l15) * 64u;
        #pragma unroll
        for (int ks = 0; ks < 2; ks++)
            xAB[ks] = (uint32_t)(((ks*2 + hi16) ^ ((lane >> 1) & 3)) << 4);
        #pragma unroll
        for (int p = 0; p < 4; p++) rowB[p] = (uint32_t)(wn + p * 16 + l15) * 64u;
    }

    auto load_stage = [&](int kc, int s) {
        const uint32_t sA = smem_base + s * GSTAGE1;
        const uint32_t sB = sA + 4096;
        // A: 64 rows x 64B, 256 cp16
        #pragma unroll
        for (int v = 0; v < 2; v++) {
            const int cid = v * 128 + tid;
            const int row = cid >> 2;
            const int c   = cid & 3;
            cp16(sA + row * 64 + ((c ^ ((row >> 1) & 3)) << 4),
                 Ap + (size_t)(bm + row) * rstride + kc * cstride + c * 8);
        }
        // B: 128 rows x 64B (hi plane, packed layout), 512 cp16
        #pragma unroll
        for (int v = 0; v < 4; v++) {
            const int cid = v * 128 + tid;
            const int row = cid >> 2;
            const int c   = cid & 3;
            cp16(sB + row * 64 + ((c ^ ((row >> 1) & 3)) << 4),
                 Bp + (((size_t)(bn + row) * 32 + kc) << 6) + c * 8);
        }
        CP_COMMIT();
    };

    float acc[2][8][4];
    #pragma unroll
    for (int i = 0; i < 2; i++)
        #pragma unroll
        for (int j = 0; j < 8; j++)
            #pragma unroll
            for (int e = 0; e < 4; e++) acc[i][j][e] = 0.f;

    load_stage(0, 0);
    load_stage(1, 1);

    int stage = 0;
    for (int i = 0; i < NCHUNK; i++) {
        if (i == NCHUNK - 1) { CP_WAIT(0); }   // exact tail wait
        else                 { CP_WAIT(1); }
        __syncthreads();

        const uint32_t sA = smem_base + stage * GSTAGE1;
        const uint32_t sB = sA + 4096;

        #pragma unroll
        for (int ks = 0; ks < 2; ks++) {
            uint32_t Ah[2][4];
            #pragma unroll
            for (int f = 0; f < 2; f++)
                ldsm4(Ah[f], sA + rowA[f] + xAB[ks]);
            #pragma unroll
            for (int ph = 0; ph < 2; ph++) {
                uint32_t Bh[4][2];
                #pragma unroll
                for (int pp = 0; pp < 2; pp++) {
                    const int p = ph * 2 + pp;
                    uint32_t q[4];
                    ldsm4(q, sB + rowB[p] + xAB[ks]);
                    Bh[2*pp][0] = q[0]; Bh[2*pp][1] = q[2];
                    Bh[2*pp+1][0] = q[1]; Bh[2*pp+1][1] = q[3];
                }
                #pragma unroll
                for (int f = 0; f < 2; f++)
                    #pragma unroll
                    for (int jj = 0; jj < 4; jj++)
                        mma_f16(acc[f][ph * 4 + jj], Ah[f], Bh[jj]);
            }
        }

        if (i + 2 < NCHUNK) {
            int ws = stage + 2; if (ws >= 3) ws -= 3;
            load_stage(i + 2, ws);
        }
        if (++stage == 3) stage = 0;
    }

    #pragma unroll
    for (int f = 0; f < 2; f++) {
        #pragma unroll
        for (int j = 0; j < 8; j++) {
            const int col = bn + wn + j * 8 + ((lane & 3) << 1);
            const float b0 = bias[col], b1 = bias[col + 1];
            #pragma unroll
            for (int half = 0; half < 2; half++) {
                const int m = bm + wm + f * 16 + (lane >> 2) + half * 8;
                float2 o;
                o.x = (acc[f][j][half * 2 + 0] + b0) * scale;
                o.y = (acc[f][j][half * 2 + 1] + b1) * scale;
                if (mode == 0) {
                    *(float2*)(outf + (size_t)m * DD + col) = o;
                } else {
                    const int b_ = m >> 10, s_ = m & 1023;
                    const int h_ = col >> 6, d_ = col & 63;
                    const size_t idx = ((size_t)(b_ * HH + h_) * SS + s_) * HD + d_;
                    uint32_t hi, lo;
                    splitpack(o.x, o.y, hi, lo);
                    *(uint32_t*)(oh + idx) = hi;
                    if (ol) *(uint32_t*)(ol + idx) = lo;
                }
            }
        }
    }
}

// Fused QKV projections (1-term A): grid (8, 128, 3).
__global__ __launch_bounds__(128, 4) void gemm_qkv(
    const __half* __restrict__ xc,
    const __half* __restrict__ wq, const __half* __restrict__ wk,
    const __half* __restrict__ wv,
    const float* __restrict__ bq, const float* __restrict__ bk,
    const float* __restrict__ bv,
    __half* qh, __half* ql, __half* kh, __half* vh)
{
    extern __shared__ char dsm[];
    const int z = blockIdx.z;
    const __half* Bp   = (z == 0) ? wq : (z == 1) ? wk : wv;
    const float* bias  = (z == 0) ? bq : (z == 1) ? bk : bv;
    __half* oh         = (z == 0) ? qh : (z == 1) ? kh : vh;
    __half* ol         = (z == 0) ? ql : nullptr;
    const float scale  = (z == 0) ? QSCALE : 1.f;
    gemm1_core(xc, 2048, 64, Bp, bias, nullptr, oh, ol, scale, 1, dsm,
               blockIdx.y << 6, blockIdx.x << 7);
}

// Output projection (1-term A, flat att layout): grid (8, 128).
__global__ __launch_bounds__(128, 4) void gemm_ao(
    const __half* __restrict__ ac, const __half* __restrict__ woc,
    const float* __restrict__ bo, float* __restrict__ out)
{
    extern __shared__ char dsm[];
    gemm1_core(ac, 1024, 32, woc, bo, out, nullptr, nullptr, 1.f, 0, dsm,
               blockIdx.y << 6, blockIdx.x << 7);
}

// ---------------------------------------------------------------------------
// Flash attention, fp16 mma.sync. Q split (2 planes); K,V,P single plane.
// 64-row q tiles, 128 threads/4 warps, grid (16,16,8), exp2-domain softmax.
// Output: single fp16 plane [row][1024].
// ---------------------------------------------------------------------------
#define FSTAGE 16384

__global__ __launch_bounds__(128) void flash_f16(
    const __half* __restrict__ qh, const __half* __restrict__ ql,
    const __half* __restrict__ kh, const __half* __restrict__ vh,
    const float* __restrict__ vb, __half* __restrict__ outp)
{
    extern __shared__ char dsm[];
    const uint32_t sb = smem_u32(dsm);

    const int tid  = threadIdx.x;
    const int wid  = tid >> 5;
    const int lane = tid & 31;
    const int qt = blockIdx.x, h = blockIdx.y, b = blockIdx.z;
    const size_t bhrow = ((size_t)b * HH + h) * SS;

    const uint32_t sQh = sb, sQl = sb + 8192;
    const uint32_t sVB = sb + 16384;
    const float* svp = (const float*)(dsm + 16384);
    const uint32_t stage_base = sb + 20480;

    auto ldplane = [&](uint32_t dst, const __half* src) {
        #pragma unroll
        for (int v = 0; v < 4; v++) {
            const int cid = v * 128 + tid;
            const int row = cid >> 3, c = cid & 7;
            cp16(dst + row * 128 + ((c ^ (row & 7)) << 4),
                 src + (size_t)row * 64 + c * 8);
        }
    };
    auto load_stage = [&](int kt, int s) {
        const uint32_t st = stage_base + (uint32_t)s * FSTAGE;
        const size_t ro = (bhrow + (size_t)kt * 64) * 64;
        ldplane(st,        kh + ro);
        ldplane(st + 8192, vh + ro);
        CP_COMMIT();
    };

    {
        const size_t qo = (bhrow + (size_t)qt * 64) * 64;
        ldplane(sQh, qh + qo);
        ldplane(sQl, ql + qo);
        #pragma unroll
        for (int v = 0; v < 2; v++) {
            const int cid = v * 128 + tid;
            cp16(sVB + cid * 16, vb + (size_t)b * SS + cid * 4);
        }
        CP_COMMIT();
    }
    load_stage(0, 0);

    const int grp = lane >> 3, rw = lane & 7;
    const int c0  = (lane & 3) << 1;
    const int qr0 = wid * 16 + (lane >> 2);
    const int qr1 = qr0 + 8;

    uint32_t rowK[4], xK[4], rowV[4], xV[4];
    #pragma unroll
    for (int i = 0; i < 4; i++) {
        rowK[i] = (uint32_t)(i * 16 + (grp >> 1) * 8 + rw) * 128u;
        xK[i]   = (uint32_t)(((2 * i + (grp & 1)) ^ rw) << 4);
        rowV[i] = (uint32_t)(i * 16 + (grp & 1) * 8 + rw) * 128u;
        xV[i]   = (uint32_t)(((2 * i + (grp >> 1)) ^ rw) << 4);
    }

    uint32_t Qh[4][4], Ql[4][4];
    float O[8][4];
    #pragma unroll
    for (int j = 0; j < 8; j++)
        #pragma unroll
        for (int e = 0; e < 4; e++) O[j][e] = 0.f;
    float mrow0 = NEG_INF, mrow1 = NEG_INF;
    float lp0 = 0.f, lp1 = 0.f;

    for (int kt = 0; kt <= qt; kt++) {
        const int s = kt & 1;
        if (kt < qt) { load_stage(kt + 1, s ^ 1); CP_WAIT(1); }
        else         { CP_WAIT(0); }
        __syncthreads();

        if (kt == 0) {
            #pragma unroll
            for (int ks = 0; ks < 4; ks++) {
                const int row = wid * 16 + (grp & 1) * 8 + rw;
                const int ch  = 2 * ks + (grp >> 1);
                const uint32_t off = row * 128 + ((ch ^ rw) << 4);
                ldsm4(Qh[ks], sQh + off);
                ldsm4(Ql[ks], sQl + off);
            }
        }

        const uint32_t stK = stage_base + (uint32_t)s * FSTAGE;
        const uint32_t stV = stK + 8192;

        float S[8][4];
        #pragma unroll
        for (int j = 0; j < 8; j++)
            #pragma unroll
            for (int e = 0; e < 4; e++) S[j][e] = 0.f;

        #pragma unroll
        for (int ks = 0; ks < 4; ks++) {
            uint32_t Bh[8][2];
            #pragma unroll
            for (int jp = 0; jp < 4; jp++) {
                uint32_t t[4];
                ldsm4(t, stK + rowK[jp] + xK[ks]);
                Bh[2*jp][0] = t[0]; Bh[2*jp][1] = t[1];
                Bh[2*jp+1][0] = t[2]; Bh[2*jp+1][1] = t[3];
            }
            #pragma unroll
            for (int j = 0; j < 8; j++) {
                mma_f16(S[j], Qh[ks], Bh[j]);
                mma_f16(S[j], Ql[ks], Bh[j]);
            }
        }

        #pragma unroll
        for (int j = 0; j < 8; j++) {
            const int k0 = j * 8 + c0, k1 = k0 + 1;
            const float p0 = svp[kt * 64 + k0];
            const float p1 = svp[kt * 64 + k1];
            S[j][0] += p0; S[j][1] += p1; S[j][2] += p0; S[j][3] += p1;
            if (kt == qt) {
                if (k0 > qr0) S[j][0] = NEG_INF;
                if (k1 > qr0) S[j][1] = NEG_INF;
                if (k0 > qr1) S[j][2] = NEG_INF;
                if (k1 > qr1) S[j][3] = NEG_INF;
            }
        }
        float rm0 = NEG_INF, rm1 = NEG_INF;
        #pragma unroll
        for (int j = 0; j < 8; j++) {
            rm0 = fmaxf(rm0, fmaxf(S[j][0], S[j][1]));
            rm1 = fmaxf(rm1, fmaxf(S[j][2], S[j][3]));
        }
        rm0 = fmaxf(rm0, __shfl_xor_sync(0xffffffffu, rm0, 1));
        rm0 = fmaxf(rm0, __shfl_xor_sync(0xffffffffu, rm0, 2));
        rm1 = fmaxf(rm1, __shfl_xor_sync(0xffffffffu, rm1, 1));
        rm1 = fmaxf(rm1, __shfl_xor_sync(0xffffffffu, rm1, 2));

        const float mn0 = fmaxf(mrow0, rm0);
        const float mn1 = fmaxf(mrow1, rm1);
        const float al0 = (mrow0 == NEG_INF) ? 0.f : exp2f(mrow0 - mn0);
        const float al1 = (mrow1 == NEG_INF) ? 0.f : exp2f(mrow1 - mn1);

        float ps0 = 0.f, ps1 = 0.f;
        #pragma unroll
        for (int j = 0; j < 8; j++) {
            float p;
            p = (S[j][0] == NEG_INF) ? 0.f : exp2f(S[j][0] - mn0); S[j][0] = p; ps0 += p;
            p = (S[j][1] == NEG_INF) ? 0.f : exp2f(S[j][1] - mn0); S[j][1] = p; ps0 += p;
            p = (S[j][2] == NEG_INF) ? 0.f : exp2f(S[j][2] - mn1); S[j][2] = p; ps1 += p;
            p = (S[j][3] == NEG_INF) ? 0.f : exp2f(S[j][3] - mn1); S[j][3] = p; ps1 += p;
        }
        lp0 = lp0 * al0 + ps0; mrow0 = mn0;
        lp1 = lp1 * al1 + ps1; mrow1 = mn1;
        #pragma unroll
        for (int j = 0; j < 8; j++) {
            O[j][0] *= al0; O[j][1] *= al0;
            O[j][2] *= al1; O[j][3] *= al1;
        }

        #pragma unroll
        for (int ks = 0; ks < 4; ks++) {
            uint32_t Ph[4];
            Ph[0] = pack2h(S[2*ks][0],   S[2*ks][1]);
            Ph[1] = pack2h(S[2*ks][2],   S[2*ks][3]);
            Ph[2] = pack2h(S[2*ks+1][0], S[2*ks+1][1]);
            Ph[3] = pack2h(S[2*ks+1][2], S[2*ks+1][3]);

            uint32_t Vh[8][2];
            #pragma unroll
            for (int jp = 0; jp < 4; jp++) {
                uint32_t t[4];
                ldsm4t(t, stV + rowV[ks] + xV[jp]);
                Vh[2*jp][0] = t[0]; Vh[2*jp][1] = t[1];
                Vh[2*jp+1][0] = t[2]; Vh[2*jp+1][1] = t[3];
            }
            #pragma unroll
            for (int j = 0; j < 8; j++)
                mma_f16(O[j], Ph, Vh[j]);
        }
        __syncthreads();
    }

    float lrow0 = lp0, lrow1 = lp1;
    lrow0 += __shfl_xor_sync(0xffffffffu, lrow0, 1);
    lrow0 += __shfl_xor_sync(0xffffffffu, lrow0, 2);
    lrow1 += __shfl_xor_sync(0xffffffffu, lrow1, 1);
    lrow1 += __shfl_xor_sync(0xffffffffu, lrow1, 2);

    const float ri0 = (lrow0 > 0.f) ? 1.f / lrow0 : 0.f;
    const float ri1 = (lrow1 > 0.f) ? 1.f / lrow1 : 0.f;
    const int m0 = b * 1024 + qt * 64 + qr0;
    const int m1 = m0 + 8;
    #pragma unroll
    for (int j = 0; j < 8; j++) {
        const int col = h * 64 + j * 8 + c0;
        *(uint32_t*)(outp + (size_t)m0 * 1024 + col) = pack2h(O[j][0] * ri0, O[j][1] * ri0);
        *(uint32_t*)(outp + (size_t)m1 * 1024 + col) = pack2h(O[j][2] * ri1, O[j][3] * ri1);
    }
}

// ---------------------------------------------------------------------------
extern "C" void kernel_launch(void* const* d_in, const int* in_sizes, int n_in,
                              void* d_out, int out_size)
{
    const float*     x   = (const float*)d_in[0];
    const long long* ids = (const long long*)d_in[1];
    const float*     Wq  = (const float*)d_in[2];
    const float*     bq  = (const float*)d_in[3];
    const float*     Wk  = (const float*)d_in[4];
    const float*     bk  = (const float*)d_in[5];
    const float*     Wv  = (const float*)d_in[6];
    const float*     bv  = (const float*)d_in[7];
    const float*     Wo  = (const float*)d_in[8];
    const float*     bo  = (const float*)d_in[9];
    float* out = (float*)d_out;

    __half *xc, *ac, *wqc, *wkc, *wvc, *woc, *qh, *ql, *kh, *vh;
    float* vb;
    cudaGetSymbolAddress((void**)&xc,  g_xc);
    cudaGetSymbolAddress((void**)&ac,  g_ac);
    cudaGetSymbolAddress((void**)&wqc, g_wqc);
    cudaGetSymbolAddress((void**)&wkc, g_wkc);
    cudaGetSymbolAddress((void**)&wvc, g_wvc);
    cudaGetSymbolAddress((void**)&woc, g_woc);
    cudaGetSymbolAddress((void**)&qh,  g_qh);
    cudaGetSymbolAddress((void**)&ql,  g_ql);
    cudaGetSymbolAddress((void**)&kh,  g_kh);
    cudaGetSymbolAddress((void**)&vh,  g_vh);
    cudaGetSymbolAddress((void**)&vb,  g_vb);

    const int g1_smem    = 3 * GSTAGE1;           // 36KB -> 4 CTAs/SM
    const int flash_smem = 20480 + 2 * FSTAGE;    // 52KB
    cudaFuncSetAttribute(gemm_qkv, cudaFuncAttributeMaxDynamicSharedMemorySize, g1_smem);
    cudaFuncSetAttribute(gemm_ao,  cudaFuncAttributeMaxDynamicSharedMemorySize, g1_smem);
    cudaFuncSetAttribute(flash_f16, cudaFuncAttributeMaxDynamicSharedMemorySize, flash_smem);

    convert_split<<<(MROWS*128)/256, 256>>>(x, xc, MROWS);
    convert_w4<<<dim3((DD*128)/256, 4), 256>>>(Wq, Wk, Wv, Wo, wqc, wkc, wvc, woc);
    pad_mask<<<MROWS/256, 256>>>(ids, vb);

    gemm_qkv<<<dim3(8, 128, 3), 128, g1_smem>>>(xc, wqc, wkc, wvc, bq, bk, bv,
                                                qh, ql, kh, vh);

    flash_f16<<<dim3(16, 16, 8), 128, flash_smem>>>(qh, ql, kh, vh, vb, ac);

    gemm_ao<<<dim3(8, 128), 128, g1_smem>>>(ac, woc, bo, out);
}

// round 16
// speedup vs baseline: 1.7214x; 1.0637x over previous
#include <cuda_runtime.h>
#include <cuda_fp16.h>
#include <math.h>
#include <stdint.h>

// Problem constants
#define BB   8
#define SS   1024
#define DD   1024
#define HH   16
#define HD   64
#define MROWS (BB*SS)   // 8192
#define NCHUNK 32       // K / 32
#define NEG_INF (-INFINITY)
#define QSCALE 0.18033688011112042f   // 0.125 * log2(e)

// Scratch (allocation-free rule: __device__ globals). All fp16 flat [row][1024].
__device__ __half g_xc [MROWS*1024];
__device__ __half g_ac [MROWS*1024];
__device__ __half g_wqc[DD*1024];
__device__ __half g_wkc[DD*1024];
__device__ __half g_wvc[DD*1024];
__device__ __half g_woc[DD*1024];
// QKV planes [B,H,S,HD] fp16 (Q pre-scaled by QSCALE)
__device__ __half g_qh[MROWS*DD];
__device__ __half g_kh[MROWS*DD];
__device__ __half g_vh[MROWS*DD];
__device__ float g_vb[MROWS];

// ---------------------------------------------------------------------------
// PTX helpers
// ---------------------------------------------------------------------------
__device__ __forceinline__ uint32_t smem_u32(const void* p) {
    uint32_t a;
    asm("{ .reg .u64 t; cvta.to.shared.u64 t, %1; cvt.u32.u64 %0, t; }" : "=r"(a) : "l"(p));
    return a;
}
__device__ __forceinline__ void cp16(uint32_t dst, const void* src) {
    asm volatile("cp.async.cg.shared.global [%0], [%1], 16;" :: "r"(dst), "l"(src));
}
#define CP_COMMIT() asm volatile("cp.async.commit_group;" ::: "memory")
#define CP_WAIT(n)  asm volatile("cp.async.wait_group %0;" :: "n"(n) : "memory")

__device__ __forceinline__ void ldsm4(uint32_t* r, uint32_t addr) {
    asm volatile("ldmatrix.sync.aligned.m8n8.x4.shared.b16 {%0,%1,%2,%3}, [%4];"
                 : "=r"(r[0]), "=r"(r[1]), "=r"(r[2]), "=r"(r[3]) : "r"(addr));
}
__device__ __forceinline__ void ldsm4t(uint32_t* r, uint32_t addr) {
    asm volatile("ldmatrix.sync.aligned.m8n8.x4.trans.shared.b16 {%0,%1,%2,%3}, [%4];"
                 : "=r"(r[0]), "=r"(r[1]), "=r"(r[2]), "=r"(r[3]) : "r"(addr));
}
__device__ __forceinline__ void mma_f16(float* d, const uint32_t* a, const uint32_t* b) {
    asm volatile("mma.sync.aligned.m16n8k16.row.col.f32.f16.f16.f32 "
                 "{%0,%1,%2,%3}, {%4,%5,%6,%7}, {%8,%9}, {%0,%1,%2,%3};"
                 : "+f"(d[0]), "+f"(d[1]), "+f"(d[2]), "+f"(d[3])
                 : "r"(a[0]), "r"(a[1]), "r"(a[2]), "r"(a[3]), "r"(b[0]), "r"(b[1]));
}
__device__ __forceinline__ uint32_t pack2h(float x, float y) {
    __half2 h2 = __floats2half2_rn(x, y);
    uint32_t u; memcpy(&u, &h2, 4); return u;
}

// ---------------------------------------------------------------------------
// fp32 -> fp16 flat convert. One thread = 8 elements.
// ---------------------------------------------------------------------------
__device__ __forceinline__ void convh_body(
    const float* __restrict__ in, __half* __restrict__ out, int g)
{
    const float* src = in + (size_t)g * 8;
    float4 f0 = *(const float4*)(src);
    float4 f1 = *(const float4*)(src + 4);
    alignas(16) __half h[8];
    h[0] = __float2half_rn(f0.x); h[1] = __float2half_rn(f0.y);
    h[2] = __float2half_rn(f0.z); h[3] = __float2half_rn(f0.w);
    h[4] = __float2half_rn(f1.x); h[5] = __float2half_rn(f1.y);
    h[6] = __float2half_rn(f1.z); h[7] = __float2half_rn(f1.w);
    *(uint4*)(out + (size_t)g * 8) = *(const uint4*)h;
}

__global__ __launch_bounds__(256) void convert_h(
    const float* __restrict__ in, __half* __restrict__ out, int n8)
{
    const int g = blockIdx.x * 256 + threadIdx.x;
    if (g < n8) convh_body(in, out, g);
}

// Fused weight converts: grid (512, 4)
__global__ __launch_bounds__(256) void convert_w4(
    const float* __restrict__ w0, const float* __restrict__ w1,
    const float* __restrict__ w2, const float* __restrict__ w3,
    __half* o0, __half* o1, __half* o2, __half* o3)
{
    const int g = blockIdx.x * 256 + threadIdx.x;
    const int z = blockIdx.y;
    const float* in = (z == 0) ? w0 : (z == 1) ? w1 : (z == 2) ? w2 : w3;
    __half* out     = (z == 0) ? o0 : (z == 1) ? o1 : (z == 2) ? o2 : o3;
    if (g < DD * 128) convh_body(in, out, g);
}

__global__ void pad_mask(const long long* __restrict__ ids, float* __restrict__ vb) {
    int i = blockIdx.x * 256 + threadIdx.x;
    if (i < MROWS) vb[i] = (ids[i] != 1LL) ? 0.f : NEG_INF;
}

// ---------------------------------------------------------------------------
// 1-term GEMM core: C = A * W^T (+bias)*scale, all fp16 flat [row][1024].
// 64x128 tile, 128 threads, 3-stage pipeline (12KB/stage), 4 CTAs/SM.
// mode 0: fp32 out [M,N]. mode 1: fp16 plane [B,H,S,HD].
// ---------------------------------------------------------------------------
#define GSTAGE1 12288

__device__ __forceinline__ void gemm1_core(
    const __half* __restrict__ Ap, const __half* __restrict__ Bp,
    const float* __restrict__ bias,
    float* __restrict__ outf, __half* __restrict__ oh,
    float scale, int mode, char* dsm, int bm, int bn)
{
    const uint32_t smem_base = smem_u32(dsm);
    const int tid  = threadIdx.x;
    const int wid  = tid >> 5;
    const int lane = tid & 31;
    const int wm = (wid & 1) << 5;
    const int wn = (wid >> 1) << 6;

    uint32_t rowA[2], rowB[4], xAB[2];
    {
        const int l15 = lane & 15, hi16 = lane >> 4;
        #pragma unroll
        for (int f = 0; f < 2; f++) rowA[f] = (uint32_t)(wm + f * 16 + l15) * 64u;
        #pragma unroll
        for (int ks = 0; ks < 2; ks++)
            xAB[ks] = (uint32_t)(((ks*2 + hi16) ^ ((lane >> 1) & 3)) << 4);
        #pragma unroll
        for (int p = 0; p < 4; p++) rowB[p] = (uint32_t)(wn + p * 16 + l15) * 64u;
    }

    auto load_stage = [&](int kc, int s) {
        const uint32_t sA = smem_base + s * GSTAGE1;
        const uint32_t sB = sA + 4096;
        // A: 64 rows x 64B
        #pragma unroll
        for (int v = 0; v < 2; v++) {
            const int cid = v * 128 + tid;
            const int row = cid >> 2;
            const int c   = cid & 3;
            cp16(sA + row * 64 + ((c ^ ((row >> 1) & 3)) << 4),
                 Ap + ((size_t)(bm + row) << 10) + kc * 32 + c * 8);
        }
        // B: 128 rows x 64B
        #pragma unroll
        for (int v = 0; v < 4; v++) {
            const int cid = v * 128 + tid;
            const int row = cid >> 2;
            const int c   = cid & 3;
            cp16(sB + row * 64 + ((c ^ ((row >> 1) & 3)) << 4),
                 Bp + ((size_t)(bn + row) << 10) + kc * 32 + c * 8);
        }
        CP_COMMIT();
    };

    float acc[2][8][4];
    #pragma unroll
    for (int i = 0; i < 2; i++)
        #pragma unroll
        for (int j = 0; j < 8; j++)
            #pragma unroll
            for (int e = 0; e < 4; e++) acc[i][j][e] = 0.f;

    load_stage(0, 0);
    load_stage(1, 1);

    int stage = 0;
    for (int i = 0; i < NCHUNK; i++) {
        if (i == NCHUNK - 1) { CP_WAIT(0); }   // exact tail wait
        else                 { CP_WAIT(1); }
        __syncthreads();

        const uint32_t sA = smem_base + stage * GSTAGE1;
        const uint32_t sB = sA + 4096;

        #pragma unroll
        for (int ks = 0; ks < 2; ks++) {
            uint32_t Ah[2][4];
            #pragma unroll
            for (int f = 0; f < 2; f++)
                ldsm4(Ah[f], sA + rowA[f] + xAB[ks]);
            #pragma unroll
            for (int ph = 0; ph < 2; ph++) {
                uint32_t Bh[4][2];
                #pragma unroll
                for (int pp = 0; pp < 2; pp++) {
                    const int p = ph * 2 + pp;
                    uint32_t q[4];
                    ldsm4(q, sB + rowB[p] + xAB[ks]);
                    Bh[2*pp][0] = q[0]; Bh[2*pp][1] = q[2];
                    Bh[2*pp+1][0] = q[1]; Bh[2*pp+1][1] = q[3];
                }
                #pragma unroll
                for (int f = 0; f < 2; f++)
                    #pragma unroll
                    for (int jj = 0; jj < 4; jj++)
                        mma_f16(acc[f][ph * 4 + jj], Ah[f], Bh[jj]);
            }
        }

        if (i + 2 < NCHUNK) {
            int ws = stage + 2; if (ws >= 3) ws -= 3;
            load_stage(i + 2, ws);
        }
        if (++stage == 3) stage = 0;
    }

    #pragma unroll
    for (int f = 0; f < 2; f++) {
        #pragma unroll
        for (int j = 0; j < 8; j++) {
            const int col = bn + wn + j * 8 + ((lane & 3) << 1);
            const float b0 = bias[col], b1 = bias[col + 1];
            #pragma unroll
            for (int half = 0; half < 2; half++) {
                const int m = bm + wm + f * 16 + (lane >> 2) + half * 8;
                float2 o;
                o.x = (acc[f][j][half * 2 + 0] + b0) * scale;
                o.y = (acc[f][j][half * 2 + 1] + b1) * scale;
                if (mode == 0) {
                    *(float2*)(outf + (size_t)m * DD + col) = o;
                } else {
                    const int b_ = m >> 10, s_ = m & 1023;
                    const int h_ = col >> 6, d_ = col & 63;
                    const size_t idx = ((size_t)(b_ * HH + h_) * SS + s_) * HD + d_;
                    *(uint32_t*)(oh + idx) = pack2h(o.x, o.y);
                }
            }
        }
    }
}

// Fused QKV projections: grid (8, 128, 3).
__global__ __launch_bounds__(128, 4) void gemm_qkv(
    const __half* __restrict__ xc,
    const __half* __restrict__ wq, const __half* __restrict__ wk,
    const __half* __restrict__ wv,
    const float* __restrict__ bq, const float* __restrict__ bk,
    const float* __restrict__ bv,
    __half* qh, __half* kh, __half* vh)
{
    extern __shared__ char dsm[];
    const int z = blockIdx.z;
    const __half* Bp   = (z == 0) ? wq : (z == 1) ? wk : wv;
    const float* bias  = (z == 0) ? bq : (z == 1) ? bk : bv;
    __half* oh         = (z == 0) ? qh : (z == 1) ? kh : vh;
    const float scale  = (z == 0) ? QSCALE : 1.f;
    gemm1_core(xc, Bp, bias, nullptr, oh, scale, 1, dsm,
               blockIdx.y << 6, blockIdx.x << 7);
}

// Output projection: grid (8, 128).
__global__ __launch_bounds__(128, 4) void gemm_ao(
    const __half* __restrict__ ac, const __half* __restrict__ woc,
    const float* __restrict__ bo, float* __restrict__ out)
{
    extern __shared__ char dsm[];
    gemm1_core(ac, woc, bo, out, nullptr, 1.f, 0, dsm,
               blockIdx.y << 6, blockIdx.x << 7);
}

// ---------------------------------------------------------------------------
// Flash attention, fp16 mma.sync, all single-plane (Q, K, V, P).
// 64-row q tiles, 128 threads/4 warps, grid (16,16,8), exp2-domain softmax.
// smem: Q 8KB + bias 4KB + 2 stages x {K,V} 16KB = 44KB -> 4 CTAs/SM.
// ---------------------------------------------------------------------------
#define FSTAGE 16384

__global__ __launch_bounds__(128) void flash_f16(
    const __half* __restrict__ qh, const __half* __restrict__ kh,
    const __half* __restrict__ vh, const float* __restrict__ vb,
    __half* __restrict__ outp)
{
    extern __shared__ char dsm[];
    const uint32_t sb = smem_u32(dsm);

    const int tid  = threadIdx.x;
    const int wid  = tid >> 5;
    const int lane = tid & 31;
    const int qt = blockIdx.x, h = blockIdx.y, b = blockIdx.z;
    const size_t bhrow = ((size_t)b * HH + h) * SS;

    const uint32_t sQh = sb;
    const uint32_t sVB = sb + 8192;
    const float* svp = (const float*)(dsm + 8192);
    const uint32_t stage_base = sb + 12288;

    auto ldplane = [&](uint32_t dst, const __half* src) {
        #pragma unroll
        for (int v = 0; v < 4; v++) {
            const int cid = v * 128 + tid;
            const int row = cid >> 3, c = cid & 7;
            cp16(dst + row * 128 + ((c ^ (row & 7)) << 4),
                 src + (size_t)row * 64 + c * 8);
        }
    };
    auto load_stage = [&](int kt, int s) {
        const uint32_t st = stage_base + (uint32_t)s * FSTAGE;
        const size_t ro = (bhrow + (size_t)kt * 64) * 64;
        ldplane(st,        kh + ro);
        ldplane(st + 8192, vh + ro);
        CP_COMMIT();
    };

    {
        ldplane(sQh, qh + (bhrow + (size_t)qt * 64) * 64);
        #pragma unroll
        for (int v = 0; v < 2; v++) {
            const int cid = v * 128 + tid;
            cp16(sVB + cid * 16, vb + (size_t)b * SS + cid * 4);
        }
        CP_COMMIT();
    }
    load_stage(0, 0);

    const int grp = lane >> 3, rw = lane & 7;
    const int c0  = (lane & 3) << 1;
    const int qr0 = wid * 16 + (lane >> 2);
    const int qr1 = qr0 + 8;

    uint32_t rowK[4], xK[4], rowV[4], xV[4];
    #pragma unroll
    for (int i = 0; i < 4; i++) {
        rowK[i] = (uint32_t)(i * 16 + (grp >> 1) * 8 + rw) * 128u;
        xK[i]   = (uint32_t)(((2 * i + (grp & 1)) ^ rw) << 4);
        rowV[i] = (uint32_t)(i * 16 + (grp & 1) * 8 + rw) * 128u;
        xV[i]   = (uint32_t)(((2 * i + (grp >> 1)) ^ rw) << 4);
    }

    uint32_t Qh[4][4];
    float O[8][4];
    #pragma unroll
    for (int j = 0; j < 8; j++)
        #pragma unroll
        for (int e = 0; e < 4; e++) O[j][e] = 0.f;
    float mrow0 = NEG_INF, mrow1 = NEG_INF;
    float lp0 = 0.f, lp1 = 0.f;

    for (int kt = 0; kt <= qt; kt++) {
        const int s = kt & 1;
        if (kt < qt) { load_stage(kt + 1, s ^ 1); CP_WAIT(1); }
        else         { CP_WAIT(0); }
        __syncthreads();

        if (kt == 0) {
            #pragma unroll
            for (int ks = 0; ks < 4; ks++) {
                const int row = wid * 16 + (grp & 1) * 8 + rw;
                const int ch  = 2 * ks + (grp >> 1);
                ldsm4(Qh[ks], sQh + row * 128 + ((ch ^ rw) << 4));
            }
        }

        const uint32_t stK = stage_base + (uint32_t)s * FSTAGE;
        const uint32_t stV = stK + 8192;

        float S[8][4];
        #pragma unroll
        for (int j = 0; j < 8; j++)
            #pragma unroll
            for (int e = 0; e < 4; e++) S[j][e] = 0.f;

        #pragma unroll
        for (int ks = 0; ks < 4; ks++) {
            uint32_t Bh[8][2];
            #pragma unroll
            for (int jp = 0; jp < 4; jp++) {
                uint32_t t[4];
                ldsm4(t, stK + rowK[jp] + xK[ks]);
                Bh[2*jp][0] = t[0]; Bh[2*jp][1] = t[1];
                Bh[2*jp+1][0] = t[2]; Bh[2*jp+1][1] = t[3];
            }
            #pragma unroll
            for (int j = 0; j < 8; j++)
                mma_f16(S[j], Qh[ks], Bh[j]);
        }

        #pragma unroll
        for (int j = 0; j < 8; j++) {
            const int k0 = j * 8 + c0, k1 = k0 + 1;
            const float p0 = svp[kt * 64 + k0];
            const float p1 = svp[kt * 64 + k1];
            S[j][0] += p0; S[j][1] += p1; S[j][2] += p0; S[j][3] += p1;
            if (kt == qt) {
                if (k0 > qr0) S[j][0] = NEG_INF;
                if (k1 > qr0) S[j][1] = NEG_INF;
                if (k0 > qr1) S[j][2] = NEG_INF;
                if (k1 > qr1) S[j][3] = NEG_INF;
            }
        }
        float rm0 = NEG_INF, rm1 = NEG_INF;
        #pragma unroll
        for (int j = 0; j < 8; j++) {
            rm0 = fmaxf(rm0, fmaxf(S[j][0], S[j][1]));
            rm1 = fmaxf(rm1, fmaxf(S[j][2], S[j][3]));
        }
        rm0 = fmaxf(rm0, __shfl_xor_sync(0xffffffffu, rm0, 1));
        rm0 = fmaxf(rm0, __shfl_xor_sync(0xffffffffu, rm0, 2));
        rm1 = fmaxf(rm1, __shfl_xor_sync(0xffffffffu, rm1, 1));
        rm1 = fmaxf(rm1, __shfl_xor_sync(0xffffffffu, rm1, 2));

        const float mn0 = fmaxf(mrow0, rm0);
        const float mn1 = fmaxf(mrow1, rm1);
        const float al0 = (mrow0 == NEG_INF) ? 0.f : exp2f(mrow0 - mn0);
        const float al1 = (mrow1 == NEG_INF) ? 0.f : exp2f(mrow1 - mn1);

        float ps0 = 0.f, ps1 = 0.f;
        #pragma unroll
        for (int j = 0; j < 8; j++) {
            float p;
            p = (S[j][0] == NEG_INF) ? 0.f : exp2f(S[j][0] - mn0); S[j][0] = p; ps0 += p;
            p = (S[j][1] == NEG_INF) ? 0.f : exp2f(S[j][1] - mn0); S[j][1] = p; ps0 += p;
            p = (S[j][2] == NEG_INF) ? 0.f : exp2f(S[j][2] - mn1); S[j][2] = p; ps1 += p;
            p = (S[j][3] == NEG_INF) ? 0.f : exp2f(S[j][3] - mn1); S[j][3] = p; ps1 += p;
        }
        lp0 = lp0 * al0 + ps0; mrow0 = mn0;
        lp1 = lp1 * al1 + ps1; mrow1 = mn1;
        #pragma unroll
        for (int j = 0; j < 8; j++) {
            O[j][0] *= al0; O[j][1] *= al0;
            O[j][2] *= al1; O[j][3] *= al1;
        }

        #pragma unroll
        for (int ks = 0; ks < 4; ks++) {
            uint32_t Ph[4];
            Ph[0] = pack2h(S[2*ks][0],   S[2*ks][1]);
            Ph[1] = pack2h(S[2*ks][2],   S[2*ks][3]);
            Ph[2] = pack2h(S[2*ks+1][0], S[2*ks+1][1]);
            Ph[3] = pack2h(S[2*ks+1][2], S[2*ks+1][3]);

            uint32_t Vh[8][2];
            #pragma unroll
            for (int jp = 0; jp < 4; jp++) {
                uint32_t t[4];
                ldsm4t(t, stV + rowV[ks] + xV[jp]);
                Vh[2*jp][0] = t[0]; Vh[2*jp][1] = t[1];
                Vh[2*jp+1][0] = t[2]; Vh[2*jp+1][1] = t[3];
            }
            #pragma unroll
            for (int j = 0; j < 8; j++)
                mma_f16(O[j], Ph, Vh[j]);
        }
        __syncthreads();
    }

    float lrow0 = lp0, lrow1 = lp1;
    lrow0 += __shfl_xor_sync(0xffffffffu, lrow0, 1);
    lrow0 += __shfl_xor_sync(0xffffffffu, lrow0, 2);
    lrow1 += __shfl_xor_sync(0xffffffffu, lrow1, 1);
    lrow1 += __shfl_xor_sync(0xffffffffu, lrow1, 2);

    const float ri0 = (lrow0 > 0.f) ? 1.f / lrow0 : 0.f;
    const float ri1 = (lrow1 > 0.f) ? 1.f / lrow1 : 0.f;
    const int m0 = b * 1024 + qt * 64 + qr0;
    const int m1 = m0 + 8;
    #pragma unroll
    for (int j = 0; j < 8; j++) {
        const int col = h * 64 + j * 8 + c0;
        *(uint32_t*)(outp + (size_t)m0 * 1024 + col) = pack2h(O[j][0] * ri0, O[j][1] * ri0);
        *(uint32_t*)(outp + (size_t)m1 * 1024 + col) = pack2h(O[j][2] * ri1, O[j][3] * ri1);
    }
}

// ---------------------------------------------------------------------------
extern "C" void kernel_launch(void* const* d_in, const int* in_sizes, int n_in,
                              void* d_out, int out_size)
{
    const float*     x   = (const float*)d_in[0];
    const long long* ids = (const long long*)d_in[1];
    const float*     Wq  = (const float*)d_in[2];
    const float*     bq  = (const float*)d_in[3];
    const float*     Wk  = (const float*)d_in[4];
    const float*     bk  = (const float*)d_in[5];
    const float*     Wv  = (const float*)d_in[6];
    const float*     bv  = (const float*)d_in[7];
    const float*     Wo  = (const float*)d_in[8];
    const float*     bo  = (const float*)d_in[9];
    float* out = (float*)d_out;

    __half *xc, *ac, *wqc, *wkc, *wvc, *woc, *qh, *kh, *vh;
    float* vb;
    cudaGetSymbolAddress((void**)&xc,  g_xc);
    cudaGetSymbolAddress((void**)&ac,  g_ac);
    cudaGetSymbolAddress((void**)&wqc, g_wqc);
    cudaGetSymbolAddress((void**)&wkc, g_wkc);
    cudaGetSymbolAddress((void**)&wvc, g_wvc);
    cudaGetSymbolAddress((void**)&woc, g_woc);
    cudaGetSymbolAddress((void**)&qh,  g_qh);
    cudaGetSymbolAddress((void**)&kh,  g_kh);
    cudaGetSymbolAddress((void**)&vh,  g_vh);
    cudaGetSymbolAddress((void**)&vb,  g_vb);

    const int g1_smem    = 3 * GSTAGE1;           // 36KB -> 4 CTAs/SM
    const int flash_smem = 12288 + 2 * FSTAGE;    // 44KB -> 4 CTAs/SM
    cudaFuncSetAttribute(gemm_qkv, cudaFuncAttributeMaxDynamicSharedMemorySize, g1_smem);
    cudaFuncSetAttribute(gemm_ao,  cudaFuncAttributeMaxDynamicSharedMemorySize, g1_smem);
    cudaFuncSetAttribute(flash_f16, cudaFuncAttributeMaxDynamicSharedMemorySize, flash_smem);

    convert_h<<<(MROWS*128)/256, 256>>>(x, xc, MROWS*128);
    convert_w4<<<dim3((DD*128)/256, 4), 256>>>(Wq, Wk, Wv, Wo, wqc, wkc, wvc, woc);
    pad_mask<<<MROWS/256, 256>>>(ids, vb);

    gemm_qkv<<<dim3(8, 128, 3), 128, g1_smem>>>(xc, wqc, wkc, wvc, bq, bk, bv,
                                                qh, kh, vh);

    flash_f16<<<dim3(16, 16, 8), 128, flash_smem>>>(qh, kh, vh, vb, ac);

    gemm_ao<<<dim3(8, 128), 128, g1_smem>>>(ac, woc, bo, out);
}

// round 17
// speedup vs baseline: 1.7378x; 1.0095x over previous
#include <cuda_runtime.h>
#include <cuda_fp16.h>
#include <math.h>
#include <stdint.h>

// Problem constants
#define BB   8
#define SS   1024
#define DD   1024
#define HH   16
#define HD   64
#define MROWS (BB*SS)   // 8192
#define NCHUNK 32       // K / 32
#define NEG_INF (-INFINITY)
#define QSCALE 0.18033688011112042f   // 0.125 * log2(e)

// Scratch (allocation-free rule: __device__ globals). All fp16 flat [row][1024].
__device__ __half g_xc [MROWS*1024];
__device__ __half g_ac [MROWS*1024];
__device__ __half g_wqc[DD*1024];
__device__ __half g_wkc[DD*1024];
__device__ __half g_wvc[DD*1024];
__device__ __half g_woc[DD*1024];
// QKV planes [B,H,S,HD] fp16 (Q pre-scaled by QSCALE)
__device__ __half g_qh[MROWS*DD];
__device__ __half g_kh[MROWS*DD];
__device__ __half g_vh[MROWS*DD];
__device__ float g_vb[MROWS];

// ---------------------------------------------------------------------------
// PTX helpers
// ---------------------------------------------------------------------------
__device__ __forceinline__ uint32_t smem_u32(const void* p) {
    uint32_t a;
    asm("{ .reg .u64 t; cvta.to.shared.u64 t, %1; cvt.u32.u64 %0, t; }" : "=r"(a) : "l"(p));
    return a;
}
__device__ __forceinline__ void cp16(uint32_t dst, const void* src) {
    asm volatile("cp.async.cg.shared.global [%0], [%1], 16;" :: "r"(dst), "l"(src));
}
#define CP_COMMIT() asm volatile("cp.async.commit_group;" ::: "memory")
#define CP_WAIT(n)  asm volatile("cp.async.wait_group %0;" :: "n"(n) : "memory")

__device__ __forceinline__ void ldsm4(uint32_t* r, uint32_t addr) {
    asm volatile("ldmatrix.sync.aligned.m8n8.x4.shared.b16 {%0,%1,%2,%3}, [%4];"
                 : "=r"(r[0]), "=r"(r[1]), "=r"(r[2]), "=r"(r[3]) : "r"(addr));
}
__device__ __forceinline__ void ldsm4t(uint32_t* r, uint32_t addr) {
    asm volatile("ldmatrix.sync.aligned.m8n8.x4.trans.shared.b16 {%0,%1,%2,%3}, [%4];"
                 : "=r"(r[0]), "=r"(r[1]), "=r"(r[2]), "=r"(r[3]) : "r"(addr));
}
__device__ __forceinline__ void mma_f16(float* d, const uint32_t* a, const uint32_t* b) {
    asm volatile("mma.sync.aligned.m16n8k16.row.col.f32.f16.f16.f32 "
                 "{%0,%1,%2,%3}, {%4,%5,%6,%7}, {%8,%9}, {%0,%1,%2,%3};"
                 : "+f"(d[0]), "+f"(d[1]), "+f"(d[2]), "+f"(d[3])
                 : "r"(a[0]), "r"(a[1]), "r"(a[2]), "r"(a[3]), "r"(b[0]), "r"(b[1]));
}
__device__ __forceinline__ uint32_t pack2h(float x, float y) {
    __half2 h2 = __floats2half2_rn(x, y);
    uint32_t u; memcpy(&u, &h2, 4); return u;
}

// ---------------------------------------------------------------------------
// fp32 -> fp16 flat convert. One thread = 8 elements.
// ---------------------------------------------------------------------------
__device__ __forceinline__ void convh_body(
    const float* __restrict__ in, __half* __restrict__ out, int g)
{
    const float* src = in + (size_t)g * 8;
    float4 f0 = *(const float4*)(src);
    float4 f1 = *(const float4*)(src + 4);
    alignas(16) __half h[8];
    h[0] = __float2half_rn(f0.x); h[1] = __float2half_rn(f0.y);
    h[2] = __float2half_rn(f0.z); h[3] = __float2half_rn(f0.w);
    h[4] = __float2half_rn(f1.x); h[5] = __float2half_rn(f1.y);
    h[6] = __float2half_rn(f1.z); h[7] = __float2half_rn(f1.w);
    *(uint4*)(out + (size_t)g * 8) = *(const uint4*)h;
}

// Fused converts: grid (512, 12). z 0-3 = weights; z 4-11 = x eighths.
__global__ __launch_bounds__(256) void convert_all(
    const float* __restrict__ x,
    const float* __restrict__ w0, const float* __restrict__ w1,
    const float* __restrict__ w2, const float* __restrict__ w3,
    __half* xc, __half* o0, __half* o1, __half* o2, __half* o3)
{
    const int g = blockIdx.x * 256 + threadIdx.x;
    const int z = blockIdx.y;
    if (z < 4) {
        const float* in = (z == 0) ? w0 : (z == 1) ? w1 : (z == 2) ? w2 : w3;
        __half* out     = (z == 0) ? o0 : (z == 1) ? o1 : (z == 2) ? o2 : o3;
        convh_body(in, out, g);                        // 512*256 threads = DD*128
    } else {
        const size_t off = (size_t)(z - 4) * 512 * 256; // eighth of MROWS*128
        convh_body(x + off * 8, xc + off * 8, g);
    }
}

__global__ void pad_mask(const long long* __restrict__ ids, float* __restrict__ vb) {
    int i = blockIdx.x * 256 + threadIdx.x;
    if (i < MROWS) vb[i] = (ids[i] != 1LL) ? 0.f : NEG_INF;
}

// ---------------------------------------------------------------------------
// 1-term GEMM core: C = A * W^T (+bias)*scale, all fp16 flat [row][1024].
// 64x128 tile, 128 threads, 3-stage pipeline (12KB/stage), 4 CTAs/SM.
// mode 0: fp32 out [M,N]. mode 1: fp16 plane [B,H,S,HD].
// ---------------------------------------------------------------------------
#define GSTAGE1 12288

__device__ __forceinline__ void gemm1_core(
    const __half* __restrict__ Ap, const __half* __restrict__ Bp,
    const float* __restrict__ bias,
    float* __restrict__ outf, __half* __restrict__ oh,
    float scale, int mode, char* dsm, int bm, int bn)
{
    const uint32_t smem_base = smem_u32(dsm);
    const int tid  = threadIdx.x;
    const int wid  = tid >> 5;
    const int lane = tid & 31;
    const int wm = (wid & 1) << 5;
    const int wn = (wid >> 1) << 6;

    uint32_t rowA[2], rowB[4], xAB[2];
    {
        const int l15 = lane & 15, hi16 = lane >> 4;
        #pragma unroll
        for (int f = 0; f < 2; f++) rowA[f] = (uint32_t)(wm + f * 16 + l15) * 64u;
        #pragma unroll
        for (int ks = 0; ks < 2; ks++)
            xAB[ks] = (uint32_t)(((ks*2 + hi16) ^ ((lane >> 1) & 3)) << 4);
        #pragma unroll
        for (int p = 0; p < 4; p++) rowB[p] = (uint32_t)(wn + p * 16 + l15) * 64u;
    }

    auto load_stage = [&](int kc, int s) {
        const uint32_t sA = smem_base + s * GSTAGE1;
        const uint32_t sB = sA + 4096;
        #pragma unroll
        for (int v = 0; v < 2; v++) {
            const int cid = v * 128 + tid;
            const int row = cid >> 2;
            const int c   = cid & 3;
            cp16(sA + row * 64 + ((c ^ ((row >> 1) & 3)) << 4),
                 Ap + ((size_t)(bm + row) << 10) + kc * 32 + c * 8);
        }
        #pragma unroll
        for (int v = 0; v < 4; v++) {
            const int cid = v * 128 + tid;
            const int row = cid >> 2;
            const int c   = cid & 3;
            cp16(sB + row * 64 + ((c ^ ((row >> 1) & 3)) << 4),
                 Bp + ((size_t)(bn + row) << 10) + kc * 32 + c * 8);
        }
        CP_COMMIT();
    };

    float acc[2][8][4];
    #pragma unroll
    for (int i = 0; i < 2; i++)
        #pragma unroll
        for (int j = 0; j < 8; j++)
            #pragma unroll
            for (int e = 0; e < 4; e++) acc[i][j][e] = 0.f;

    load_stage(0, 0);
    load_stage(1, 1);

    int stage = 0;
    for (int i = 0; i < NCHUNK; i++) {
        if (i == NCHUNK - 1) { CP_WAIT(0); }   // exact tail wait
        else                 { CP_WAIT(1); }
        __syncthreads();

        const uint32_t sA = smem_base + stage * GSTAGE1;
        const uint32_t sB = sA + 4096;

        #pragma unroll
        for (int ks = 0; ks < 2; ks++) {
            uint32_t Ah[2][4];
            #pragma unroll
            for (int f = 0; f < 2; f++)
                ldsm4(Ah[f], sA + rowA[f] + xAB[ks]);
            #pragma unroll
            for (int ph = 0; ph < 2; ph++) {
                uint32_t Bh[4][2];
                #pragma unroll
                for (int pp = 0; pp < 2; pp++) {
                    const int p = ph * 2 + pp;
                    uint32_t q[4];
                    ldsm4(q, sB + rowB[p] + xAB[ks]);
                    Bh[2*pp][0] = q[0]; Bh[2*pp][1] = q[2];
                    Bh[2*pp+1][0] = q[1]; Bh[2*pp+1][1] = q[3];
                }
                #pragma unroll
                for (int f = 0; f < 2; f++)
                    #pragma unroll
                    for (int jj = 0; jj < 4; jj++)
                        mma_f16(acc[f][ph * 4 + jj], Ah[f], Bh[jj]);
            }
        }

        if (i + 2 < NCHUNK) {
            int ws = stage + 2; if (ws >= 3) ws -= 3;
            load_stage(i + 2, ws);
        }
        if (++stage == 3) stage = 0;
    }

    #pragma unroll
    for (int f = 0; f < 2; f++) {
        #pragma unroll
        for (int j = 0; j < 8; j++) {
            const int col = bn + wn + j * 8 + ((lane & 3) << 1);
            const float b0 = bias[col], b1 = bias[col + 1];
            #pragma unroll
            for (int half = 0; half < 2; half++) {
                const int m = bm + wm + f * 16 + (lane >> 2) + half * 8;
                float2 o;
                o.x = (acc[f][j][half * 2 + 0] + b0) * scale;
                o.y = (acc[f][j][half * 2 + 1] + b1) * scale;
                if (mode == 0) {
                    *(float2*)(outf + (size_t)m * DD + col) = o;
                } else {
                    const int b_ = m >> 10, s_ = m & 1023;
                    const int h_ = col >> 6, d_ = col & 63;
                    const size_t idx = ((size_t)(b_ * HH + h_) * SS + s_) * HD + d_;
                    *(uint32_t*)(oh + idx) = pack2h(o.x, o.y);
                }
            }
        }
    }
}

// Fused QKV projections: grid (8, 128, 3).
__global__ __launch_bounds__(128, 4) void gemm_qkv(
    const __half* __restrict__ xc,
    const __half* __restrict__ wq, const __half* __restrict__ wk,
    const __half* __restrict__ wv,
    const float* __restrict__ bq, const float* __restrict__ bk,
    const float* __restrict__ bv,
    __half* qh, __half* kh, __half* vh)
{
    extern __shared__ char dsm[];
    const int z = blockIdx.z;
    const __half* Bp   = (z == 0) ? wq : (z == 1) ? wk : wv;
    const float* bias  = (z == 0) ? bq : (z == 1) ? bk : bv;
    __half* oh         = (z == 0) ? qh : (z == 1) ? kh : vh;
    const float scale  = (z == 0) ? QSCALE : 1.f;
    gemm1_core(xc, Bp, bias, nullptr, oh, scale, 1, dsm,
               blockIdx.y << 6, blockIdx.x << 7);
}

// Output projection: grid (8, 128).
__global__ __launch_bounds__(128, 4) void gemm_ao(
    const __half* __restrict__ ac, const __half* __restrict__ woc,
    const float* __restrict__ bo, float* __restrict__ out)
{
    extern __shared__ char dsm[];
    gemm1_core(ac, woc, bo, out, nullptr, 1.f, 0, dsm,
               blockIdx.y << 6, blockIdx.x << 7);
}

// ---------------------------------------------------------------------------
// Flash attention, fp16 mma.sync, all single-plane (Q, K, V, P).
// 64-row q tiles, 128 threads/4 warps, grid (16,16,8), exp2-domain softmax.
// qt reversed (longest blocks first) for tail-optimal scheduling.
// smem: Q 8KB + bias 4KB + 2 stages x {K,V} 16KB = 44KB -> 4 CTAs/SM.
// ---------------------------------------------------------------------------
#define FSTAGE 16384

__global__ __launch_bounds__(128) void flash_f16(
    const __half* __restrict__ qh, const __half* __restrict__ kh,
    const __half* __restrict__ vh, const float* __restrict__ vb,
    __half* __restrict__ outp)
{
    extern __shared__ char dsm[];
    const uint32_t sb = smem_u32(dsm);

    const int tid  = threadIdx.x;
    const int wid  = tid >> 5;
    const int lane = tid & 31;
    const int qt = (SS/64 - 1) - blockIdx.x;   // longest-job-first
    const int h = blockIdx.y, b = blockIdx.z;
    const size_t bhrow = ((size_t)b * HH + h) * SS;

    const uint32_t sQh = sb;
    const uint32_t sVB = sb + 8192;
    const float* svp = (const float*)(dsm + 8192);
    const uint32_t stage_base = sb + 12288;

    auto ldplane = [&](uint32_t dst, const __half* src) {
        #pragma unroll
        for (int v = 0; v < 4; v++) {
            const int cid = v * 128 + tid;
            const int row = cid >> 3, c = cid & 7;
            cp16(dst + row * 128 + ((c ^ (row & 7)) << 4),
                 src + (size_t)row * 64 + c * 8);
        }
    };
    auto load_stage = [&](int kt, int s) {
        const uint32_t st = stage_base + (uint32_t)s * FSTAGE;
        const size_t ro = (bhrow + (size_t)kt * 64) * 64;
        ldplane(st,        kh + ro);
        ldplane(st + 8192, vh + ro);
        CP_COMMIT();
    };

    {
        ldplane(sQh, qh + (bhrow + (size_t)qt * 64) * 64);
        #pragma unroll
        for (int v = 0; v < 2; v++) {
            const int cid = v * 128 + tid;
            cp16(sVB + cid * 16, vb + (size_t)b * SS + cid * 4);
        }
        CP_COMMIT();
    }
    load_stage(0, 0);

    const int grp = lane >> 3, rw = lane & 7;
    const int c0  = (lane & 3) << 1;
    const int qr0 = wid * 16 + (lane >> 2);
    const int qr1 = qr0 + 8;

    uint32_t rowK[4], xK[4], rowV[4], xV[4];
    #pragma unroll
    for (int i = 0; i < 4; i++) {
        rowK[i] = (uint32_t)(i * 16 + (grp >> 1) * 8 + rw) * 128u;
        xK[i]   = (uint32_t)(((2 * i + (grp & 1)) ^ rw) << 4);
        rowV[i] = (uint32_t)(i * 16 + (grp & 1) * 8 + rw) * 128u;
        xV[i]   = (uint32_t)(((2 * i + (grp >> 1)) ^ rw) << 4);
    }

    uint32_t Qh[4][4];
    float O[8][4];
    #pragma unroll
    for (int j = 0; j < 8; j++)
        #pragma unroll
        for (int e = 0; e < 4; e++) O[j][e] = 0.f;
    float mrow0 = NEG_INF, mrow1 = NEG_INF;
    float lp0 = 0.f, lp1 = 0.f;

    for (int kt = 0; kt <= qt; kt++) {
        const int s = kt & 1;
        if (kt < qt) { load_stage(kt + 1, s ^ 1); CP_WAIT(1); }
        else         { CP_WAIT(0); }
        __syncthreads();

        if (kt == 0) {
            #pragma unroll
            for (int ks = 0; ks < 4; ks++) {
                const int row = wid * 16 + (grp & 1) * 8 + rw;
                const int ch  = 2 * ks + (grp >> 1);
                ldsm4(Qh[ks], sQh + row * 128 + ((ch ^ rw) << 4));
            }
        }

        const uint32_t stK = stage_base + (uint32_t)s * FSTAGE;
        const uint32_t stV = stK + 8192;

        float S[8][4];
        #pragma unroll
        for (int j = 0; j < 8; j++)
            #pragma unroll
            for (int e = 0; e < 4; e++) S[j][e] = 0.f;

        #pragma unroll
        for (int ks = 0; ks < 4; ks++) {
            uint32_t Bh[8][2];
            #pragma unroll
            for (int jp = 0; jp < 4; jp++) {
                uint32_t t[4];
                ldsm4(t, stK + rowK[jp] + xK[ks]);
                Bh[2*jp][0] = t[0]; Bh[2*jp][1] = t[1];
                Bh[2*jp+1][0] = t[2]; Bh[2*jp+1][1] = t[3];
            }
            #pragma unroll
            for (int j = 0; j < 8; j++)
                mma_f16(S[j], Qh[ks], Bh[j]);
        }

        #pragma unroll
        for (int j = 0; j < 8; j++) {
            const int k0 = j * 8 + c0, k1 = k0 + 1;
            const float p0 = svp[kt * 64 + k0];
            const float p1 = svp[kt * 64 + k1];
            S[j][0] += p0; S[j][1] += p1; S[j][2] += p0; S[j][3] += p1;
            if (kt == qt) {
                if (k0 > qr0) S[j][0] = NEG_INF;
                if (k1 > qr0) S[j][1] = NEG_INF;
                if (k0 > qr1) S[j][2] = NEG_INF;
                if (k1 > qr1) S[j][3] = NEG_INF;
            }
        }
        float rm0 = NEG_INF, rm1 = NEG_INF;
        #pragma unroll
        for (int j = 0; j < 8; j++) {
            rm0 = fmaxf(rm0, fmaxf(S[j][0], S[j][1]));
            rm1 = fmaxf(rm1, fmaxf(S[j][2], S[j][3]));
        }
        rm0 = fmaxf(rm0, __shfl_xor_sync(0xffffffffu, rm0, 1));
        rm0 = fmaxf(rm0, __shfl_xor_sync(0xffffffffu, rm0, 2));
        rm1 = fmaxf(rm1, __shfl_xor_sync(0xffffffffu, rm1, 1));
        rm1 = fmaxf(rm1, __shfl_xor_sync(0xffffffffu, rm1, 2));

        const float mn0 = fmaxf(mrow0, rm0);
        const float mn1 = fmaxf(mrow1, rm1);
        const float al0 = (mrow0 == NEG_INF) ? 0.f : exp2f(mrow0 - mn0);
        const float al1 = (mrow1 == NEG_INF) ? 0.f : exp2f(mrow1 - mn1);

        float ps0 = 0.f, ps1 = 0.f;
        #pragma unroll
        for (int j = 0; j < 8; j++) {
            float p;
            p = (S[j][0] == NEG_INF) ? 0.f : exp2f(S[j][0] - mn0); S[j][0] = p; ps0 += p;
            p = (S[j][1] == NEG_INF) ? 0.f : exp2f(S[j][1] - mn0); S[j][1] = p; ps0 += p;
            p = (S[j][2] == NEG_INF) ? 0.f : exp2f(S[j][2] - mn1); S[j][2] = p; ps1 += p;
            p = (S[j][3] == NEG_INF) ? 0.f : exp2f(S[j][3] - mn1); S[j][3] = p; ps1 += p;
        }
        lp0 = lp0 * al0 + ps0; mrow0 = mn0;
        lp1 = lp1 * al1 + ps1; mrow1 = mn1;
        #pragma unroll
        for (int j = 0; j < 8; j++) {
            O[j][0] *= al0; O[j][1] *= al0;
            O[j][2] *= al1; O[j][3] *= al1;
        }

        #pragma unroll
        for (int ks = 0; ks < 4; ks++) {
            uint32_t Ph[4];
            Ph[0] = pack2h(S[2*ks][0],   S[2*ks][1]);
            Ph[1] = pack2h(S[2*ks][2],   S[2*ks][3]);
            Ph[2] = pack2h(S[2*ks+1][0], S[2*ks+1][1]);
            Ph[3] = pack2h(S[2*ks+1][2], S[2*ks+1][3]);

            uint32_t Vh[8][2];
            #pragma unroll
            for (int jp = 0; jp < 4; jp++) {
                uint32_t t[4];
                ldsm4t(t, stV + rowV[ks] + xV[jp]);
                Vh[2*jp][0] = t[0]; Vh[2*jp][1] = t[1];
                Vh[2*jp+1][0] = t[2]; Vh[2*jp+1][1] = t[3];
            }
            #pragma unroll
            for (int j = 0; j < 8; j++)
                mma_f16(O[j], Ph, Vh[j]);
        }
        __syncthreads();
    }

    float lrow0 = lp0, lrow1 = lp1;
    lrow0 += __shfl_xor_sync(0xffffffffu, lrow0, 1);
    lrow0 += __shfl_xor_sync(0xffffffffu, lrow0, 2);
    lrow1 += __shfl_xor_sync(0xffffffffu, lrow1, 1);
    lrow1 += __shfl_xor_sync(0xffffffffu, lrow1, 2);

    const float ri0 = (lrow0 > 0.f) ? 1.f / lrow0 : 0.f;
    const float ri1 = (lrow1 > 0.f) ? 1.f / lrow1 : 0.f;
    const int m0 = b * 1024 + qt * 64 + qr0;
    const int m1 = m0 + 8;
    #pragma unroll
    for (int j = 0; j < 8; j++) {
        const int col = h * 64 + j * 8 + c0;
        *(uint32_t*)(outp + (size_t)m0 * 1024 + col) = pack2h(O[j][0] * ri0, O[j][1] * ri0);
        *(uint32_t*)(outp + (size_t)m1 * 1024 + col) = pack2h(O[j][2] * ri1, O[j][3] * ri1);
    }
}

// ---------------------------------------------------------------------------
extern "C" void kernel_launch(void* const* d_in, const int* in_sizes, int n_in,
                              void* d_out, int out_size)
{
    const float*     x   = (const float*)d_in[0];
    const long long* ids = (const long long*)d_in[1];
    const float*     Wq  = (const float*)d_in[2];
    const float*     bq  = (const float*)d_in[3];
    const float*     Wk  = (const float*)d_in[4];
    const float*     bk  = (const float*)d_in[5];
    const float*     Wv  = (const float*)d_in[6];
    const float*     bv  = (const float*)d_in[7];
    const float*     Wo  = (const float*)d_in[8];
    const float*     bo  = (const float*)d_in[9];
    float* out = (float*)d_out;

    __half *xc, *ac, *wqc, *wkc, *wvc, *woc, *qh, *kh, *vh;
    float* vb;
    cudaGetSymbolAddress((void**)&xc,  g_xc);
    cudaGetSymbolAddress((void**)&ac,  g_ac);
    cudaGetSymbolAddress((void**)&wqc, g_wqc);
    cudaGetSymbolAddress((void**)&wkc, g_wkc);
    cudaGetSymbolAddress((void**)&wvc, g_wvc);
    cudaGetSymbolAddress((void**)&woc, g_woc);
    cudaGetSymbolAddress((void**)&qh,  g_qh);
    cudaGetSymbolAddress((void**)&kh,  g_kh);
    cudaGetSymbolAddress((void**)&vh,  g_vh);
    cudaGetSymbolAddress((void**)&vb,  g_vb);

    const int g1_smem    = 3 * GSTAGE1;           // 36KB -> 4 CTAs/SM
    const int flash_smem = 12288 + 2 * FSTAGE;    // 44KB -> 4 CTAs/SM
    cudaFuncSetAttribute(gemm_qkv, cudaFuncAttributeMaxDynamicSharedMemorySize, g1_smem);
    cudaFuncSetAttribute(gemm_ao,  cudaFuncAttributeMaxDynamicSharedMemorySize, g1_smem);
    cudaFuncSetAttribute(flash_f16, cudaFuncAttributeMaxDynamicSharedMemorySize, flash_smem);

    convert_all<<<dim3(512, 12), 256>>>(x, Wq, Wk, Wv, Wo, xc, wqc, wkc, wvc, woc);
    pad_mask<<<MROWS/256, 256>>>(ids, vb);

    gemm_qkv<<<dim3(8, 128, 3), 128, g1_smem>>>(xc, wqc, wkc, wvc, bq, bk, bv,
                                                qh, kh, vh);

    flash_f16<<<dim3(16, 16, 8), 128, flash_smem>>>(qh, kh, vh, vb, ac);

    gemm_ao<<<dim3(8, 128), 128, g1_smem>>>(ac, woc, bo, out);
}